// round 4
// baseline (speedup 1.0000x reference)
#include <cuda_runtime.h>
#include <math.h>

// ---------------- problem constants ----------------
constexpr int N       = 50000;
constexpr int E       = 200000;
constexpr int D_E     = 32;
constexpr int N_FRAG  = 10000;
constexpr int N_GRAPH = 2000;
constexpr float BN_EPS = 1e-5f;

// ---------------- scratch (device globals; no allocation allowed) ----------------
__device__ float g_agg [(size_t)N * 288];   // max fin = 288
__device__ float g_h1  [(size_t)N * 256];
__device__ float g_h2  [(size_t)N * 256];
__device__ float g_hin [(size_t)N * 256];   // BN output -> next layer input / pooling input
__device__ float g_agge[(size_t)N * 32];    // sum over in-edges of relu(edge_attr) (layer-invariant)
__device__ float g_stats[512];              // [0:256) sum, [256:512) sumsq
__device__ float g_scale[256];
__device__ float g_bias [256];
__device__ float g_cnt  [N_FRAG + N_GRAPH];

// ---------------- helpers ----------------
__global__ void k_zero(float* p, int n) {
    for (int i = blockIdx.x * blockDim.x + threadIdx.x; i < n; i += gridDim.x * blockDim.x)
        p[i] = 0.f;
}

// edge-feature aggregate: g_agge[dst] += relu(edge_attr[e])   (once per launch)
__global__ void k_edge_agg(const float* __restrict__ ea, const int* __restrict__ ei) {
    int i = blockIdx.x * blockDim.x + threadIdx.x;
    if (i >= E * D_E) return;
    int e = i >> 5, c = i & 31;
    float v = fmaxf(ea[i], 0.f);
    int d = ei[E + e];
    atomicAdd(&g_agge[(size_t)d * D_E + c], v);
}

// agg[:, :DIN] = in (residual), agg[:, DIN:FIN] = g_agge
template<int DIN, int FIN>
__global__ void k_init_agg(const float* __restrict__ in) {
    int i = blockIdx.x * blockDim.x + threadIdx.x;
    if (i >= N * FIN) return;
    int n = i / FIN, c = i - n * FIN;
    g_agg[i] = (c < DIN) ? in[(size_t)n * DIN + c] : g_agge[(size_t)n * D_E + (c - DIN)];
}

// agg[dst, :DIN] += relu(in[src, :DIN])
template<int DIN, int FIN>
__global__ void k_scatter(const float* __restrict__ in, const int* __restrict__ ei) {
    long long i = (long long)blockIdx.x * blockDim.x + threadIdx.x;
    if (i >= (long long)E * DIN) return;
    int e = (int)(i / DIN), c = (int)(i - (long long)e * DIN);
    int s = ei[e], d = ei[E + e];
    float v = fmaxf(in[(size_t)s * DIN + c], 0.f);
    atomicAdd(&g_agg[(size_t)d * FIN + c], v);
}

// C[M,256] = A[M,K] @ B[K,256] + bias  (optional relu). 64x64 tile, 4x4 per thread.
template<int K, bool RELU>
__global__ void k_sgemm(const float* __restrict__ A, const float* __restrict__ B,
                        const float* __restrict__ bias, float* __restrict__ C, int M) {
    constexpr int NC = 256;
    __shared__ float As[16][65];   // [k][m]
    __shared__ float Bs[16][65];   // [k][n]
    int bm = blockIdx.x * 64, bn = blockIdx.y * 64;
    int tid = threadIdx.x;
    int tr = tid >> 4, tc = tid & 15;
    float acc[4][4] = {};
    for (int k0 = 0; k0 < K; k0 += 16) {
        #pragma unroll
        for (int i = tid; i < 64 * 16; i += 256) {
            int r = i >> 4, kk = i & 15;
            float v = 0.f;
            if (bm + r < M) v = A[(size_t)(bm + r) * K + k0 + kk];
            As[kk][r] = v;
        }
        #pragma unroll
        for (int i = tid; i < 16 * 64; i += 256) {
            int kk = i >> 6, nn = i & 63;
            Bs[kk][nn] = B[(size_t)(k0 + kk) * NC + bn + nn];
        }
        __syncthreads();
        #pragma unroll
        for (int kk = 0; kk < 16; kk++) {
            float a[4], b[4];
            #pragma unroll
            for (int u = 0; u < 4; u++) a[u] = As[kk][tr * 4 + u];
            #pragma unroll
            for (int u = 0; u < 4; u++) b[u] = Bs[kk][tc * 4 + u];
            #pragma unroll
            for (int u = 0; u < 4; u++)
                #pragma unroll
                for (int v = 0; v < 4; v++) acc[u][v] += a[u] * b[v];
        }
        __syncthreads();
    }
    #pragma unroll
    for (int u = 0; u < 4; u++) {
        int r = bm + tr * 4 + u;
        if (r >= M) continue;
        #pragma unroll
        for (int v = 0; v < 4; v++) {
            int c = bn + tc * 4 + v;
            float val = acc[u][v] + bias[c];
            if (RELU) val = fmaxf(val, 0.f);
            C[(size_t)r * NC + c] = val;
        }
    }
}

// per-column sum / sumsq over h2 (already relu'd)
__global__ void k_stats(const float* __restrict__ h) {
    int c = threadIdx.x;                     // 256 threads = 256 columns
    int rows = (N + gridDim.x - 1) / gridDim.x;
    int r0 = blockIdx.x * rows;
    int r1 = min(r0 + rows, N);
    float s = 0.f, sq = 0.f;
    for (int r = r0; r < r1; r++) {
        float v = h[(size_t)r * 256 + c];
        s += v; sq += v * v;
    }
    atomicAdd(&g_stats[c], s);
    atomicAdd(&g_stats[256 + c], sq);
}

__global__ void k_bn_finalize(const float* __restrict__ g, const float* __restrict__ beta) {
    int c = threadIdx.x;
    float mu  = g_stats[c] * (1.f / N);
    float var = g_stats[256 + c] * (1.f / N) - mu * mu;
    float sc  = g[c] * rsqrtf(var + BN_EPS);
    g_scale[c] = sc;
    g_bias[c]  = beta[c] - mu * sc;
}

__global__ void k_bn_apply(const float* __restrict__ h) {
    int i = blockIdx.x * blockDim.x + threadIdx.x;
    if (i >= N * 256) return;
    int c = i & 255;
    g_hin[i] = h[i] * g_scale[c] + g_bias[c];
}

__global__ void k_count(const int* __restrict__ frag, const int* __restrict__ graph) {
    int i = blockIdx.x * blockDim.x + threadIdx.x;
    if (i >= N) return;
    atomicAdd(&g_cnt[frag[i]], 1.f);
    atomicAdd(&g_cnt[N_FRAG + graph[i]], 1.f);
}

__global__ void k_pool(const int* __restrict__ frag, const int* __restrict__ graph,
                       float* __restrict__ out) {
    int i = blockIdx.x * blockDim.x + threadIdx.x;
    if (i >= N * 256) return;
    int n = i >> 8, c = i & 255;
    float v = g_hin[i];
    int bf = frag[n];
    int bg = graph[n];
    float wf = rsqrtf(fmaxf(g_cnt[bf], 1.f));
    float wg = rsqrtf(fmaxf(g_cnt[N_FRAG + bg], 1.f));
    atomicAdd(&out[(size_t)bf * 256 + c], v * wf);
    atomicAdd(&out[(size_t)(N_FRAG + bg) * 256 + c], v * wg);
}

// ---------------- launch ----------------
static inline int cdiv(long long a, int b) { return (int)((a + b - 1) / b); }

extern "C" void kernel_launch(void* const* d_in, const int* in_sizes, int n_in,
                              void* d_out, int out_size) {
    // ---- resolve input ordering by size signature ----
    // edge_index is the unique entry of size 2*E = 400000 elements.
    int idx_ei = -1;
    for (int i = 0; i < n_in; i++) if (in_sizes[i] == 2 * E) { idx_ei = i; break; }

    // index tables for the two plausible metadata orderings
    // dict/signature order: x, edge_attr, edge_index, frag, graph, then per layer w1,b1,w2,b2,g,beta
    // alphabetical order:   b1_0..2, b2_0..2, beta_0..2, edge_attr, edge_index, frag_batch,
    //                       g_0..2, graph_batch, w1_0..2, w2_0..2, x
    int ix, iea, ifr, igr;
    int iw1[3], ib1[3], iw2[3], ib2[3], ig[3], ibeta[3];
    if (idx_ei == 10) {              // alphabetical
        ix = 22; iea = 9; ifr = 11; igr = 15;
        for (int l = 0; l < 3; l++) {
            ib1[l] = 0 + l; ib2[l] = 3 + l; ibeta[l] = 6 + l;
            ig[l] = 12 + l; iw1[l] = 16 + l; iw2[l] = 19 + l;
        }
    } else {                         // dict / reference-signature order (idx_ei == 2 expected)
        idx_ei = 2;
        ix = 0; iea = 1; ifr = 3; igr = 4;
        for (int l = 0; l < 3; l++) {
            iw1[l] = 5 + 6 * l + 0; ib1[l] = 5 + 6 * l + 1;
            iw2[l] = 5 + 6 * l + 2; ib2[l] = 5 + 6 * l + 3;
            ig[l]  = 5 + 6 * l + 4; ibeta[l] = 5 + 6 * l + 5;
        }
    }

    const float* x     = (const float*)d_in[ix];
    const float* ea    = (const float*)d_in[iea];
    const int*   ei    = (const int*)d_in[idx_ei];    // JAX x64 disabled -> int32
    const int*   frag  = (const int*)d_in[ifr];
    const int*   graph = (const int*)d_in[igr];
    const float* w1[3]; const float* b1[3]; const float* w2[3];
    const float* b2[3]; const float* gg[3]; const float* bb[3];
    for (int l = 0; l < 3; l++) {
        w1[l] = (const float*)d_in[iw1[l]];
        b1[l] = (const float*)d_in[ib1[l]];
        w2[l] = (const float*)d_in[iw2[l]];
        b2[l] = (const float*)d_in[ib2[l]];
        gg[l] = (const float*)d_in[ig[l]];
        bb[l] = (const float*)d_in[ibeta[l]];
    }
    float* out = (float*)d_out;

    float* p_agge; cudaGetSymbolAddress((void**)&p_agge, g_agge);
    float* p_stats; cudaGetSymbolAddress((void**)&p_stats, g_stats);
    float* p_cnt;  cudaGetSymbolAddress((void**)&p_cnt, g_cnt);
    float* p_agg;  cudaGetSymbolAddress((void**)&p_agg, g_agg);
    float* p_h1;   cudaGetSymbolAddress((void**)&p_h1, g_h1);
    float* p_h2;   cudaGetSymbolAddress((void**)&p_h2, g_h2);
    float* p_hin;  cudaGetSymbolAddress((void**)&p_hin, g_hin);

    const int T = 256;

    // edge-feature aggregate (layer-invariant)
    k_zero<<<cdiv(N * D_E, T), T>>>(p_agge, N * D_E);
    k_edge_agg<<<cdiv((long long)E * D_E, T), T>>>(ea, ei);

    // ---- layer 0: din=128, fin=160 ----
    k_init_agg<128, 160><<<cdiv((long long)N * 160, T), T>>>(x);
    k_scatter<128, 160><<<cdiv((long long)E * 128, T), T>>>(x, ei);
    {
        dim3 g1(cdiv(N, 64), 4);
        k_sgemm<160, true ><<<g1, 256>>>(p_agg, w1[0], b1[0], p_h1, N);
        k_sgemm<256, true ><<<g1, 256>>>(p_h1, w2[0], b2[0], p_h2, N);
    }
    k_zero<<<2, 256>>>(p_stats, 512);
    k_stats<<<256, 256>>>(p_h2);
    k_bn_finalize<<<1, 256>>>(gg[0], bb[0]);
    k_bn_apply<<<cdiv((long long)N * 256, T), T>>>(p_h2);

    // ---- layers 1,2: din=256, fin=288 ----
    for (int l = 1; l < 3; l++) {
        k_init_agg<256, 288><<<cdiv((long long)N * 288, T), T>>>(p_hin);
        k_scatter<256, 288><<<cdiv((long long)E * 256, T), T>>>(p_hin, ei);
        dim3 g1(cdiv(N, 64), 4);
        k_sgemm<288, true ><<<g1, 256>>>(p_agg, w1[l], b1[l], p_h1, N);
        k_sgemm<256, true ><<<g1, 256>>>(p_h1, w2[l], b2[l], p_h2, N);
        k_zero<<<2, 256>>>(p_stats, 512);
        k_stats<<<256, 256>>>(p_h2);
        k_bn_finalize<<<1, 256>>>(gg[l], bb[l]);
        k_bn_apply<<<cdiv((long long)N * 256, T), T>>>(p_h2);
    }

    // ---- pooling ----
    k_zero<<<cdiv(N_FRAG + N_GRAPH, T), T>>>(p_cnt, N_FRAG + N_GRAPH);
    k_zero<<<cdiv(out_size, T), T>>>(out, out_size);
    k_count<<<cdiv(N, T), T>>>(frag, graph);
    k_pool<<<cdiv((long long)N * 256, T), T>>>(frag, graph, out);
}

// round 6
// speedup vs baseline: 2.2449x; 2.2449x over previous
#include <cuda_runtime.h>
#include <math.h>

// ---------------- problem constants ----------------
constexpr int N       = 50000;
constexpr int E       = 200000;
constexpr int D_E     = 32;
constexpr int N_FRAG  = 10000;
constexpr int N_GRAPH = 2000;
constexpr float BN_EPS = 1e-5f;

// ---------------- scratch (device globals; no allocation allowed) ----------------
__device__ __align__(16) float g_agg [(size_t)N * 288];   // max fin = 288
__device__ __align__(16) float g_h1  [(size_t)N * 256];
__device__ __align__(16) float g_h2  [(size_t)N * 256];
__device__ __align__(16) float g_hin [(size_t)N * 256];
__device__ __align__(16) float g_agge[(size_t)N * 32];
__device__ float g_stats[512];
__device__ float g_scale[256];
__device__ float g_bias [256];
__device__ float g_cnt  [N_FRAG + N_GRAPH];

// ---------------- small helpers ----------------
__global__ void k_zero(float* p, int n) {
    for (int i = blockIdx.x * blockDim.x + threadIdx.x; i < n; i += gridDim.x * blockDim.x)
        p[i] = 0.f;
}

__device__ __forceinline__ void red_v4(float* p, float a, float b, float c, float d) {
    asm volatile("red.global.add.v4.f32 [%0], {%1,%2,%3,%4};"
                 :: "l"(p), "f"(a), "f"(b), "f"(c), "f"(d) : "memory");
}

__device__ __forceinline__ unsigned f2tf32(float x) {
    unsigned r;
    asm("cvt.rna.tf32.f32 %0, %1;" : "=r"(r) : "f"(x));
    return r;
}
// hi/lo split: hi = tf32(v), lo = tf32(v - hi)
__device__ __forceinline__ void split_tf32(float v, unsigned& hi, unsigned& lo) {
    hi = f2tf32(v);
    lo = f2tf32(v - __uint_as_float(hi));
}

// edge-feature aggregate: g_agge[dst] += relu(edge_attr[e])  (layer-invariant)
__global__ void k_edge_agg(const float* __restrict__ ea, const int* __restrict__ ei) {
    int i = blockIdx.x * blockDim.x + threadIdx.x;
    if (i >= E * (D_E / 4)) return;
    int e = i >> 3, c4 = (i & 7) * 4;
    float4 v = *(const float4*)(ea + (size_t)e * D_E + c4);
    int d = ei[E + e];
    red_v4(&g_agge[(size_t)d * D_E + c4],
           fmaxf(v.x, 0.f), fmaxf(v.y, 0.f), fmaxf(v.z, 0.f), fmaxf(v.w, 0.f));
}

// agg[:, :DIN] = in (residual), agg[:, DIN:FIN] = g_agge  (float4)
template<int DIN, int FIN>
__global__ void k_init_agg(const float* __restrict__ in) {
    int i = blockIdx.x * blockDim.x + threadIdx.x;
    constexpr int CG = FIN / 4;
    if (i >= N * CG) return;
    int n = i / CG, c = (i - n * CG) * 4;
    float4 v;
    if (c < DIN) v = *(const float4*)(in + (size_t)n * DIN + c);
    else         v = *(const float4*)(&g_agge[(size_t)n * D_E + (c - DIN)]);
    *(float4*)(&g_agg[(size_t)n * FIN + c]) = v;
}

// agg[dst, :DIN] += relu(in[src, :DIN])  via vector red
template<int DIN, int FIN>
__global__ void k_scatter(const float* __restrict__ in, const int* __restrict__ ei) {
    int i = blockIdx.x * blockDim.x + threadIdx.x;
    constexpr int CG = DIN / 4;
    if (i >= E * CG) return;
    int e = i / CG, c = (i - e * CG) * 4;
    int s = ei[e], d = ei[E + e];
    float4 v = *(const float4*)(in + (size_t)s * DIN + c);
    red_v4(&g_agg[(size_t)d * FIN + c],
           fmaxf(v.x, 0.f), fmaxf(v.y, 0.f), fmaxf(v.z, 0.f), fmaxf(v.w, 0.f));
}

// ---------------- 3xTF32 tensor-core GEMM ----------------
// C[M,256] = relu(A[M,K] @ B[K,256] + bias). Block 128x128x16, 8 warps (2x4),
// warp tile 64x32 via m16n8k8 tf32 mma with hi/lo error compensation:
//   C += Ahi*Bhi + Ahi*Blo + Alo*Bhi   (~fp32 precision)
template<int K, bool RELU>
__global__ __launch_bounds__(256) void k_mma(const float* __restrict__ A,
                                             const float* __restrict__ B,
                                             const float* __restrict__ bias,
                                             float* __restrict__ C, int M) {
    constexpr int NC = 256;
    __shared__ unsigned AsH[128 * 20], AsL[128 * 20];  // [m][k], stride 20
    __shared__ unsigned BsH[16 * 136], BsL[16 * 136];  // [k][n], stride 136
    const int bm = blockIdx.x * 128, bn = blockIdx.y * 128;
    const int tid = threadIdx.x, lane = tid & 31, wid = tid >> 5;
    const int wm = (wid >> 2) * 64, wn = (wid & 3) * 32;

    float acc[4][4][4];
    #pragma unroll
    for (int a = 0; a < 4; a++)
        #pragma unroll
        for (int b = 0; b < 4; b++)
            #pragma unroll
            for (int c = 0; c < 4; c++) acc[a][b][c] = 0.f;

    const int a_cg = tid & 3;      // 4 float4 groups = 16 k
    const int a_r0 = tid >> 2;     // rows 0..63, step 64
    const int b_cg = tid & 31;     // 32 float4 groups = 128 n
    const int b_k0 = tid >> 5;     // k 0..7, step 8

    for (int k0 = 0; k0 < K; k0 += 16) {
        // A tile 128x16 -> hi/lo smem
        #pragma unroll
        for (int q = 0; q < 2; q++) {
            int r = a_r0 + 64 * q;
            float4 v = make_float4(0.f, 0.f, 0.f, 0.f);
            if (bm + r < M) v = *(const float4*)(A + (size_t)(bm + r) * K + k0 + a_cg * 4);
            uint4 h, l;
            split_tf32(v.x, h.x, l.x); split_tf32(v.y, h.y, l.y);
            split_tf32(v.z, h.z, l.z); split_tf32(v.w, h.w, l.w);
            *(uint4*)(&AsH[r * 20 + a_cg * 4]) = h;
            *(uint4*)(&AsL[r * 20 + a_cg * 4]) = l;
        }
        // B tile 16x128 -> hi/lo smem
        #pragma unroll
        for (int q = 0; q < 2; q++) {
            int k = b_k0 + 8 * q;
            float4 v = *(const float4*)(B + (size_t)(k0 + k) * NC + bn + b_cg * 4);
            uint4 h, l;
            split_tf32(v.x, h.x, l.x); split_tf32(v.y, h.y, l.y);
            split_tf32(v.z, h.z, l.z); split_tf32(v.w, h.w, l.w);
            *(uint4*)(&BsH[k * 136 + b_cg * 4]) = h;
            *(uint4*)(&BsL[k * 136 + b_cg * 4]) = l;
        }
        __syncthreads();

        #pragma unroll
        for (int kk = 0; kk < 2; kk++) {
            const int kb = kk * 8;
            unsigned ah[4][4], al[4][4], bh[4][2], bl[4][2];
            #pragma unroll
            for (int mf = 0; mf < 4; mf++) {
                int m0 = wm + mf * 16 + (lane >> 2);
                int kc = kb + (lane & 3);
                ah[mf][0] = AsH[m0 * 20 + kc];       al[mf][0] = AsL[m0 * 20 + kc];
                ah[mf][1] = AsH[(m0 + 8) * 20 + kc]; al[mf][1] = AsL[(m0 + 8) * 20 + kc];
                ah[mf][2] = AsH[m0 * 20 + kc + 4];   al[mf][2] = AsL[m0 * 20 + kc + 4];
                ah[mf][3] = AsH[(m0 + 8) * 20 + kc + 4]; al[mf][3] = AsL[(m0 + 8) * 20 + kc + 4];
            }
            #pragma unroll
            for (int nf = 0; nf < 4; nf++) {
                int n0 = wn + nf * 8 + (lane >> 2);
                int kr = kb + (lane & 3);
                bh[nf][0] = BsH[kr * 136 + n0];       bl[nf][0] = BsL[kr * 136 + n0];
                bh[nf][1] = BsH[(kr + 4) * 136 + n0]; bl[nf][1] = BsL[(kr + 4) * 136 + n0];
            }
            #pragma unroll
            for (int mf = 0; mf < 4; mf++)
                #pragma unroll
                for (int nf = 0; nf < 4; nf++) {
                    float* c = acc[mf][nf];
                    // lo terms first, hi*hi last
                    asm volatile(
                        "mma.sync.aligned.m16n8k8.row.col.f32.tf32.tf32.f32 "
                        "{%0,%1,%2,%3}, {%4,%5,%6,%7}, {%8,%9}, {%0,%1,%2,%3};"
                        : "+f"(c[0]), "+f"(c[1]), "+f"(c[2]), "+f"(c[3])
                        : "r"(al[mf][0]), "r"(al[mf][1]), "r"(al[mf][2]), "r"(al[mf][3]),
                          "r"(bh[nf][0]), "r"(bh[nf][1]));
                    asm volatile(
                        "mma.sync.aligned.m16n8k8.row.col.f32.tf32.tf32.f32 "
                        "{%0,%1,%2,%3}, {%4,%5,%6,%7}, {%8,%9}, {%0,%1,%2,%3};"
                        : "+f"(c[0]), "+f"(c[1]), "+f"(c[2]), "+f"(c[3])
                        : "r"(ah[mf][0]), "r"(ah[mf][1]), "r"(ah[mf][2]), "r"(ah[mf][3]),
                          "r"(bl[nf][0]), "r"(bl[nf][1]));
                    asm volatile(
                        "mma.sync.aligned.m16n8k8.row.col.f32.tf32.tf32.f32 "
                        "{%0,%1,%2,%3}, {%4,%5,%6,%7}, {%8,%9}, {%0,%1,%2,%3};"
                        : "+f"(c[0]), "+f"(c[1]), "+f"(c[2]), "+f"(c[3])
                        : "r"(ah[mf][0]), "r"(ah[mf][1]), "r"(ah[mf][2]), "r"(ah[mf][3]),
                          "r"(bh[nf][0]), "r"(bh[nf][1]));
                }
        }
        __syncthreads();
    }

    // epilogue: bias + relu, float2 stores
    #pragma unroll
    for (int mf = 0; mf < 4; mf++) {
        int r0 = bm + wm + mf * 16 + (lane >> 2);
        #pragma unroll
        for (int nf = 0; nf < 4; nf++) {
            int cc = bn + wn + nf * 8 + (lane & 3) * 2;
            float b0 = bias[cc], b1 = bias[cc + 1];
            float* c = acc[mf][nf];
            if (r0 < M) {
                float v0 = c[0] + b0, v1 = c[1] + b1;
                if (RELU) { v0 = fmaxf(v0, 0.f); v1 = fmaxf(v1, 0.f); }
                *(float2*)(C + (size_t)r0 * NC + cc) = make_float2(v0, v1);
            }
            if (r0 + 8 < M) {
                float v0 = c[2] + b0, v1 = c[3] + b1;
                if (RELU) { v0 = fmaxf(v0, 0.f); v1 = fmaxf(v1, 0.f); }
                *(float2*)(C + (size_t)(r0 + 8) * NC + cc) = make_float2(v0, v1);
            }
        }
    }
}

// per-column sum / sumsq over h2 (already relu'd)
__global__ void k_stats(const float* __restrict__ h) {
    int c = threadIdx.x;
    int rows = (N + gridDim.x - 1) / gridDim.x;
    int r0 = blockIdx.x * rows;
    int r1 = min(r0 + rows, N);
    float s = 0.f, sq = 0.f;
    for (int r = r0; r < r1; r++) {
        float v = h[(size_t)r * 256 + c];
        s += v; sq += v * v;
    }
    atomicAdd(&g_stats[c], s);
    atomicAdd(&g_stats[256 + c], sq);
}

__global__ void k_bn_finalize(const float* __restrict__ g, const float* __restrict__ beta) {
    int c = threadIdx.x;
    float mu  = g_stats[c] * (1.f / N);
    float var = g_stats[256 + c] * (1.f / N) - mu * mu;
    float sc  = g[c] * rsqrtf(var + BN_EPS);
    g_scale[c] = sc;
    g_bias[c]  = beta[c] - mu * sc;
}

__global__ void k_bn_apply(const float* __restrict__ h) {
    int i = blockIdx.x * blockDim.x + threadIdx.x;
    if (i >= N * 64) return;
    int c = (i & 63) * 4;
    float4 v = *(const float4*)(h + (size_t)i * 4);
    v.x = v.x * g_scale[c]     + g_bias[c];
    v.y = v.y * g_scale[c + 1] + g_bias[c + 1];
    v.z = v.z * g_scale[c + 2] + g_bias[c + 2];
    v.w = v.w * g_scale[c + 3] + g_bias[c + 3];
    *(float4*)(&g_hin[(size_t)i * 4]) = v;
}

__global__ void k_count(const int* __restrict__ frag, const int* __restrict__ graph) {
    int i = blockIdx.x * blockDim.x + threadIdx.x;
    if (i >= N) return;
    atomicAdd(&g_cnt[frag[i]], 1.f);
    atomicAdd(&g_cnt[N_FRAG + graph[i]], 1.f);
}

__global__ void k_pool(const int* __restrict__ frag, const int* __restrict__ graph,
                       float* __restrict__ out) {
    int i = blockIdx.x * blockDim.x + threadIdx.x;
    if (i >= N * 64) return;
    int n = i >> 6, c = (i & 63) * 4;
    float4 v = *(const float4*)(&g_hin[(size_t)n * 256 + c]);
    int bf = frag[n];
    int bg = graph[n];
    float wf = rsqrtf(fmaxf(g_cnt[bf], 1.f));
    float wg = rsqrtf(fmaxf(g_cnt[N_FRAG + bg], 1.f));
    red_v4(out + (size_t)bf * 256 + c, v.x * wf, v.y * wf, v.z * wf, v.w * wf);
    red_v4(out + (size_t)(N_FRAG + bg) * 256 + c, v.x * wg, v.y * wg, v.z * wg, v.w * wg);
}

// ---------------- launch ----------------
static inline int cdiv(long long a, int b) { return (int)((a + b - 1) / b); }

extern "C" void kernel_launch(void* const* d_in, const int* in_sizes, int n_in,
                              void* d_out, int out_size) {
    // resolve input ordering by size signature (edge_index is unique 2*E entry)
    int idx_ei = -1;
    for (int i = 0; i < n_in; i++) if (in_sizes[i] == 2 * E) { idx_ei = i; break; }

    int ix, iea, ifr, igr;
    int iw1[3], ib1[3], iw2[3], ib2[3], ig[3], ibeta[3];
    if (idx_ei == 10) {              // alphabetical
        ix = 22; iea = 9; ifr = 11; igr = 15;
        for (int l = 0; l < 3; l++) {
            ib1[l] = 0 + l; ib2[l] = 3 + l; ibeta[l] = 6 + l;
            ig[l] = 12 + l; iw1[l] = 16 + l; iw2[l] = 19 + l;
        }
    } else {                         // dict / reference-signature order
        idx_ei = 2;
        ix = 0; iea = 1; ifr = 3; igr = 4;
        for (int l = 0; l < 3; l++) {
            iw1[l] = 5 + 6 * l + 0; ib1[l] = 5 + 6 * l + 1;
            iw2[l] = 5 + 6 * l + 2; ib2[l] = 5 + 6 * l + 3;
            ig[l]  = 5 + 6 * l + 4; ibeta[l] = 5 + 6 * l + 5;
        }
    }

    const float* x     = (const float*)d_in[ix];
    const float* ea    = (const float*)d_in[iea];
    const int*   ei    = (const int*)d_in[idx_ei];
    const int*   frag  = (const int*)d_in[ifr];
    const int*   graph = (const int*)d_in[igr];
    const float* w1[3]; const float* b1[3]; const float* w2[3];
    const float* b2[3]; const float* gg[3]; const float* bb[3];
    for (int l = 0; l < 3; l++) {
        w1[l] = (const float*)d_in[iw1[l]];
        b1[l] = (const float*)d_in[ib1[l]];
        w2[l] = (const float*)d_in[iw2[l]];
        b2[l] = (const float*)d_in[ib2[l]];
        gg[l] = (const float*)d_in[ig[l]];
        bb[l] = (const float*)d_in[ibeta[l]];
    }
    float* out = (float*)d_out;

    float* p_agge; cudaGetSymbolAddress((void**)&p_agge, g_agge);
    float* p_stats; cudaGetSymbolAddress((void**)&p_stats, g_stats);
    float* p_cnt;  cudaGetSymbolAddress((void**)&p_cnt, g_cnt);
    float* p_agg;  cudaGetSymbolAddress((void**)&p_agg, g_agg);
    float* p_h1;   cudaGetSymbolAddress((void**)&p_h1, g_h1);
    float* p_h2;   cudaGetSymbolAddress((void**)&p_h2, g_h2);
    float* p_hin;  cudaGetSymbolAddress((void**)&p_hin, g_hin);

    const int T = 256;
    dim3 gemm_grid(cdiv(N, 128), 2);

    // edge-feature aggregate (layer-invariant)
    k_zero<<<cdiv(N * D_E, T), T>>>(p_agge, N * D_E);
    k_edge_agg<<<cdiv((long long)E * 8, T), T>>>(ea, ei);

    // ---- layer 0: din=128, fin=160 ----
    k_init_agg<128, 160><<<cdiv((long long)N * 40, T), T>>>(x);
    k_scatter<128, 160><<<cdiv((long long)E * 32, T), T>>>(x, ei);
    k_mma<160, true><<<gemm_grid, 256>>>(p_agg, w1[0], b1[0], p_h1, N);
    k_mma<256, true><<<gemm_grid, 256>>>(p_h1, w2[0], b2[0], p_h2, N);
    k_zero<<<2, 256>>>(p_stats, 512);
    k_stats<<<256, 256>>>(p_h2);
    k_bn_finalize<<<1, 256>>>(gg[0], bb[0]);
    k_bn_apply<<<cdiv((long long)N * 64, T), T>>>(p_h2);

    // ---- layers 1,2: din=256, fin=288 ----
    for (int l = 1; l < 3; l++) {
        k_init_agg<256, 288><<<cdiv((long long)N * 72, T), T>>>(p_hin);
        k_scatter<256, 288><<<cdiv((long long)E * 64, T), T>>>(p_hin, ei);
        k_mma<288, true><<<gemm_grid, 256>>>(p_agg, w1[l], b1[l], p_h1, N);
        k_mma<256, true><<<gemm_grid, 256>>>(p_h1, w2[l], b2[l], p_h2, N);
        k_zero<<<2, 256>>>(p_stats, 512);
        k_stats<<<256, 256>>>(p_h2);
        k_bn_finalize<<<1, 256>>>(gg[l], bb[l]);
        k_bn_apply<<<cdiv((long long)N * 64, T), T>>>(p_h2);
    }

    // ---- pooling ----
    k_zero<<<cdiv(N_FRAG + N_GRAPH, T), T>>>(p_cnt, N_FRAG + N_GRAPH);
    k_zero<<<cdiv(out_size, T), T>>>(out, out_size);
    k_count<<<cdiv(N, T), T>>>(frag, graph);
    k_pool<<<cdiv((long long)N * 64, T), T>>>(frag, graph, out);
}

// round 7
// speedup vs baseline: 2.4956x; 1.1117x over previous
#include <cuda_runtime.h>
#include <math.h>

// ---------------- problem constants ----------------
constexpr int N       = 50000;
constexpr int E       = 200000;
constexpr int D_E     = 32;
constexpr int N_FRAG  = 10000;
constexpr int N_GRAPH = 2000;
constexpr float BN_EPS = 1e-5f;

// ---------------- scratch (device globals; no allocation allowed) ----------------
__device__ __align__(16) float g_agg [(size_t)N * 288];   // max fin = 288
__device__ __align__(16) float g_h1  [(size_t)N * 256];
__device__ __align__(16) float g_h2  [(size_t)N * 256];
__device__ __align__(16) float g_agge[(size_t)N * 32];
__device__ float g_stats[512];
__device__ float g_scale[256];
__device__ float g_bias [256];
__device__ float g_cnt  [N_FRAG + N_GRAPH];

// ---------------- small helpers ----------------
__global__ void k_zero(float* p, int n) {
    for (int i = blockIdx.x * blockDim.x + threadIdx.x; i < n; i += gridDim.x * blockDim.x)
        p[i] = 0.f;
}

__device__ __forceinline__ void red_v4(float* p, float a, float b, float c, float d) {
    asm volatile("red.global.add.v4.f32 [%0], {%1,%2,%3,%4};"
                 :: "l"(p), "f"(a), "f"(b), "f"(c), "f"(d) : "memory");
}

__device__ __forceinline__ unsigned f2tf32(float x) {
    unsigned r;
    asm("cvt.rna.tf32.f32 %0, %1;" : "=r"(r) : "f"(x));
    return r;
}
// hi/lo split: hi = tf32(v), lo = tf32(v - hi)
__device__ __forceinline__ void split_tf32(float v, unsigned& hi, unsigned& lo) {
    hi = f2tf32(v);
    lo = f2tf32(v - __uint_as_float(hi));
}

#define MMA_TF32(c, a, b)                                                     \
    asm volatile(                                                             \
        "mma.sync.aligned.m16n8k8.row.col.f32.tf32.tf32.f32 "                 \
        "{%0,%1,%2,%3}, {%4,%5,%6,%7}, {%8,%9}, {%0,%1,%2,%3};"               \
        : "+f"((c)[0]), "+f"((c)[1]), "+f"((c)[2]), "+f"((c)[3])              \
        : "r"((a)[0]), "r"((a)[1]), "r"((a)[2]), "r"((a)[3]),                 \
          "r"((b)[0]), "r"((b)[1]))

// edge-feature aggregate: g_agge[dst] += relu(edge_attr[e])  (layer-invariant)
__global__ void k_edge_agg(const float* __restrict__ ea, const int* __restrict__ ei) {
    int i = blockIdx.x * blockDim.x + threadIdx.x;
    if (i >= E * (D_E / 4)) return;
    int e = i >> 3, c4 = (i & 7) * 4;
    float4 v = *(const float4*)(ea + (size_t)e * D_E + c4);
    int d = ei[E + e];
    red_v4(&g_agge[(size_t)d * D_E + c4],
           fmaxf(v.x, 0.f), fmaxf(v.y, 0.f), fmaxf(v.z, 0.f), fmaxf(v.w, 0.f));
}

// agg[:, :DIN] = affine?(in*scale+bias):in (residual), agg[:, DIN:FIN] = g_agge
template<int DIN, int FIN, bool AFF>
__global__ void k_init_agg(const float* __restrict__ in) {
    int i = blockIdx.x * blockDim.x + threadIdx.x;
    constexpr int CG = FIN / 4;
    if (i >= N * CG) return;
    int n = i / CG, c = (i - n * CG) * 4;
    float4 v;
    if (c < DIN) {
        v = *(const float4*)(in + (size_t)n * DIN + c);
        if (AFF) {
            v.x = fmaf(v.x, g_scale[c],     g_bias[c]);
            v.y = fmaf(v.y, g_scale[c + 1], g_bias[c + 1]);
            v.z = fmaf(v.z, g_scale[c + 2], g_bias[c + 2]);
            v.w = fmaf(v.w, g_scale[c + 3], g_bias[c + 3]);
        }
    } else {
        v = *(const float4*)(&g_agge[(size_t)n * D_E + (c - DIN)]);
    }
    *(float4*)(&g_agg[(size_t)n * FIN + c]) = v;
}

// agg[dst, :DIN] += relu(affine?(in*scale+bias):in [src])
template<int DIN, int FIN, bool AFF>
__global__ void k_scatter(const float* __restrict__ in, const int* __restrict__ ei) {
    int i = blockIdx.x * blockDim.x + threadIdx.x;
    constexpr int CG = DIN / 4;
    if (i >= E * CG) return;
    int e = i / CG, c = (i - e * CG) * 4;
    int s = ei[e], d = ei[E + e];
    float4 v = *(const float4*)(in + (size_t)s * DIN + c);
    if (AFF) {
        v.x = fmaf(v.x, g_scale[c],     g_bias[c]);
        v.y = fmaf(v.y, g_scale[c + 1], g_bias[c + 1]);
        v.z = fmaf(v.z, g_scale[c + 2], g_bias[c + 2]);
        v.w = fmaf(v.w, g_scale[c + 3], g_bias[c + 3]);
    }
    red_v4(&g_agg[(size_t)d * FIN + c],
           fmaxf(v.x, 0.f), fmaxf(v.y, 0.f), fmaxf(v.z, 0.f), fmaxf(v.w, 0.f));
}

// ---------------- 3xTF32 tensor-core GEMM, cp.async double-buffered ----------------
// C[M,256] = relu(A[M,K] @ B[K,256] + bias). Block 128x128x32, 8 warps (2x4),
// warp tile 64x32 via m16n8k8 tf32 mma, hi/lo split in registers:
//   C += Alo*Bhi + Ahi*Blo + Ahi*Bhi
template<int K, bool RELU>
__global__ __launch_bounds__(256, 2) void k_mma(const float* __restrict__ A,
                                                const float* __restrict__ B,
                                                const float* __restrict__ bias,
                                                float* __restrict__ C, int M) {
    constexpr int NC  = 256;
    constexpr int LDA = 36, LDB = 136;
    constexpr int A_T = 128 * LDA;       // 4608 floats
    constexpr int B_T = 32 * LDB;        // 4352 floats
    constexpr int STG = A_T + B_T;       // 8960 floats per stage
    extern __shared__ float dsm[];
    const unsigned sbase = (unsigned)__cvta_generic_to_shared(dsm);

    const int bm = blockIdx.x * 128, bn = blockIdx.y * 128;
    const int tid = threadIdx.x, lane = tid & 31, wid = tid >> 5;
    const int wm = (wid >> 2) * 64, wn = (wid & 3) * 32;
    const int qr = lane >> 2, ql = lane & 3;

    const int a_cg = tid & 7,  a_r0 = tid >> 3;   // A: 8 grp x 32 rows (x4)
    const int b_cg = tid & 31, b_k0 = tid >> 5;   // B: 32 grp x 8 rows (x4)

    auto issue = [&](int k0, int stage) {
        unsigned sb = sbase + stage * (STG * 4);
        #pragma unroll
        for (int q = 0; q < 4; q++) {
            int r = a_r0 + 32 * q;
            int gr = bm + r;
            const float* src = A + (size_t)(gr < M ? gr : M - 1) * K + k0 + a_cg * 4;
            int sz = gr < M ? 16 : 0;
            unsigned dst = sb + (unsigned)(r * LDA + a_cg * 4) * 4;
            asm volatile("cp.async.cg.shared.global [%0], [%1], 16, %2;"
                         :: "r"(dst), "l"(src), "r"(sz));
        }
        #pragma unroll
        for (int q = 0; q < 4; q++) {
            int k = b_k0 + 8 * q;
            const float* src = B + (size_t)(k0 + k) * NC + bn + b_cg * 4;
            unsigned dst = sb + (unsigned)(A_T + k * LDB + b_cg * 4) * 4;
            asm volatile("cp.async.cg.shared.global [%0], [%1], 16, 16;"
                         :: "r"(dst), "l"(src));
        }
        asm volatile("cp.async.commit_group;");
    };

    float acc[4][4][4] = {};
    constexpr int NIT = K / 32;

    issue(0, 0);
    for (int it = 0; it < NIT; ++it) {
        if (it + 1 < NIT) {
            issue((it + 1) * 32, (it + 1) & 1);
            asm volatile("cp.async.wait_group 1;");
        } else {
            asm volatile("cp.async.wait_group 0;");
        }
        __syncthreads();
        const float* As = dsm + (it & 1) * STG;
        const float* Bs = As + A_T;

        #pragma unroll
        for (int kk = 0; kk < 4; kk++) {
            const int kc = kk * 8 + ql;
            unsigned bh[4][2], bl[4][2];
            #pragma unroll
            for (int nf = 0; nf < 4; nf++) {
                int n0 = wn + nf * 8 + qr;
                split_tf32(Bs[kc * LDB + n0],       bh[nf][0], bl[nf][0]);
                split_tf32(Bs[(kc + 4) * LDB + n0], bh[nf][1], bl[nf][1]);
            }
            #pragma unroll
            for (int mf = 0; mf < 4; mf++) {
                int m0 = wm + mf * 16 + qr;
                unsigned ah[4], al[4];
                split_tf32(As[m0 * LDA + kc],           ah[0], al[0]);
                split_tf32(As[(m0 + 8) * LDA + kc],     ah[1], al[1]);
                split_tf32(As[m0 * LDA + kc + 4],       ah[2], al[2]);
                split_tf32(As[(m0 + 8) * LDA + kc + 4], ah[3], al[3]);
                #pragma unroll
                for (int nf = 0; nf < 4; nf++) {
                    float* c = acc[mf][nf];
                    MMA_TF32(c, al, bh[nf]);
                    MMA_TF32(c, ah, bl[nf]);
                    MMA_TF32(c, ah, bh[nf]);
                }
            }
        }
        __syncthreads();
    }

    // epilogue: bias + relu, float2 stores
    #pragma unroll
    for (int mf = 0; mf < 4; mf++) {
        int r0 = bm + wm + mf * 16 + qr;
        #pragma unroll
        for (int nf = 0; nf < 4; nf++) {
            int cc = bn + wn + nf * 8 + ql * 2;
            float b0 = bias[cc], b1 = bias[cc + 1];
            float* c = acc[mf][nf];
            if (r0 < M) {
                float v0 = c[0] + b0, v1 = c[1] + b1;
                if (RELU) { v0 = fmaxf(v0, 0.f); v1 = fmaxf(v1, 0.f); }
                *(float2*)(C + (size_t)r0 * NC + cc) = make_float2(v0, v1);
            }
            if (r0 + 8 < M) {
                float v0 = c[2] + b0, v1 = c[3] + b1;
                if (RELU) { v0 = fmaxf(v0, 0.f); v1 = fmaxf(v1, 0.f); }
                *(float2*)(C + (size_t)(r0 + 8) * NC + cc) = make_float2(v0, v1);
            }
        }
    }
}

// per-column sum / sumsq over h2 (already relu'd)
__global__ void k_stats(const float* __restrict__ h) {
    int c = threadIdx.x;
    int rows = (N + gridDim.x - 1) / gridDim.x;
    int r0 = blockIdx.x * rows;
    int r1 = min(r0 + rows, N);
    float s = 0.f, sq = 0.f;
    for (int r = r0; r < r1; r++) {
        float v = h[(size_t)r * 256 + c];
        s += v; sq += v * v;
    }
    atomicAdd(&g_stats[c], s);
    atomicAdd(&g_stats[256 + c], sq);
}

__global__ void k_bn_finalize(const float* __restrict__ g, const float* __restrict__ beta) {
    int c = threadIdx.x;
    float mu  = g_stats[c] * (1.f / N);
    float var = g_stats[256 + c] * (1.f / N) - mu * mu;
    float sc  = g[c] * rsqrtf(var + BN_EPS);
    g_scale[c] = sc;
    g_bias[c]  = beta[c] - mu * sc;
}

__global__ void k_count(const int* __restrict__ frag, const int* __restrict__ graph) {
    int i = blockIdx.x * blockDim.x + threadIdx.x;
    if (i >= N) return;
    atomicAdd(&g_cnt[frag[i]], 1.f);
    atomicAdd(&g_cnt[N_FRAG + graph[i]], 1.f);
}

// pool reads raw h2 and applies final BN affine inline
__global__ void k_pool(const int* __restrict__ frag, const int* __restrict__ graph,
                       const float* __restrict__ h, float* __restrict__ out) {
    int i = blockIdx.x * blockDim.x + threadIdx.x;
    if (i >= N * 64) return;
    int n = i >> 6, c = (i & 63) * 4;
    float4 v = *(const float4*)(h + (size_t)n * 256 + c);
    v.x = fmaf(v.x, g_scale[c],     g_bias[c]);
    v.y = fmaf(v.y, g_scale[c + 1], g_bias[c + 1]);
    v.z = fmaf(v.z, g_scale[c + 2], g_bias[c + 2]);
    v.w = fmaf(v.w, g_scale[c + 3], g_bias[c + 3]);
    int bf = frag[n];
    int bg = graph[n];
    float wf = rsqrtf(fmaxf(g_cnt[bf], 1.f));
    float wg = rsqrtf(fmaxf(g_cnt[N_FRAG + bg], 1.f));
    red_v4(out + (size_t)bf * 256 + c, v.x * wf, v.y * wf, v.z * wf, v.w * wf);
    red_v4(out + (size_t)(N_FRAG + bg) * 256 + c, v.x * wg, v.y * wg, v.z * wg, v.w * wg);
}

// ---------------- launch ----------------
static inline int cdiv(long long a, int b) { return (int)((a + b - 1) / b); }
constexpr int GEMM_SMEM = 2 * (128 * 36 + 32 * 136) * 4;   // 71680 bytes

extern "C" void kernel_launch(void* const* d_in, const int* in_sizes, int n_in,
                              void* d_out, int out_size) {
    // resolve input ordering by size signature (edge_index is unique 2*E entry)
    int idx_ei = -1;
    for (int i = 0; i < n_in; i++) if (in_sizes[i] == 2 * E) { idx_ei = i; break; }

    int ix, iea, ifr, igr;
    int iw1[3], ib1[3], iw2[3], ib2[3], ig[3], ibeta[3];
    if (idx_ei == 10) {              // alphabetical
        ix = 22; iea = 9; ifr = 11; igr = 15;
        for (int l = 0; l < 3; l++) {
            ib1[l] = 0 + l; ib2[l] = 3 + l; ibeta[l] = 6 + l;
            ig[l] = 12 + l; iw1[l] = 16 + l; iw2[l] = 19 + l;
        }
    } else {                         // dict / reference-signature order
        idx_ei = 2;
        ix = 0; iea = 1; ifr = 3; igr = 4;
        for (int l = 0; l < 3; l++) {
            iw1[l] = 5 + 6 * l + 0; ib1[l] = 5 + 6 * l + 1;
            iw2[l] = 5 + 6 * l + 2; ib2[l] = 5 + 6 * l + 3;
            ig[l]  = 5 + 6 * l + 4; ibeta[l] = 5 + 6 * l + 5;
        }
    }

    const float* x     = (const float*)d_in[ix];
    const float* ea    = (const float*)d_in[iea];
    const int*   ei    = (const int*)d_in[idx_ei];
    const int*   frag  = (const int*)d_in[ifr];
    const int*   graph = (const int*)d_in[igr];
    const float* w1[3]; const float* b1[3]; const float* w2[3];
    const float* b2[3]; const float* gg[3]; const float* bb[3];
    for (int l = 0; l < 3; l++) {
        w1[l] = (const float*)d_in[iw1[l]];
        b1[l] = (const float*)d_in[ib1[l]];
        w2[l] = (const float*)d_in[iw2[l]];
        b2[l] = (const float*)d_in[ib2[l]];
        gg[l] = (const float*)d_in[ig[l]];
        bb[l] = (const float*)d_in[ibeta[l]];
    }
    float* out = (float*)d_out;

    float* p_agge; cudaGetSymbolAddress((void**)&p_agge, g_agge);
    float* p_stats; cudaGetSymbolAddress((void**)&p_stats, g_stats);
    float* p_cnt;  cudaGetSymbolAddress((void**)&p_cnt, g_cnt);
    float* p_agg;  cudaGetSymbolAddress((void**)&p_agg, g_agg);
    float* p_h1;   cudaGetSymbolAddress((void**)&p_h1, g_h1);
    float* p_h2;   cudaGetSymbolAddress((void**)&p_h2, g_h2);

    cudaFuncSetAttribute(k_mma<160, true>, cudaFuncAttributeMaxDynamicSharedMemorySize, GEMM_SMEM);
    cudaFuncSetAttribute(k_mma<256, true>, cudaFuncAttributeMaxDynamicSharedMemorySize, GEMM_SMEM);
    cudaFuncSetAttribute(k_mma<288, true>, cudaFuncAttributeMaxDynamicSharedMemorySize, GEMM_SMEM);

    const int T = 256;
    dim3 gemm_grid(cdiv(N, 128), 2);

    // edge-feature aggregate (layer-invariant)
    k_zero<<<cdiv(N * D_E, T), T>>>(p_agge, N * D_E);
    k_edge_agg<<<cdiv((long long)E * 8, T), T>>>(ea, ei);

    // ---- layer 0: din=128, fin=160 ----
    k_init_agg<128, 160, false><<<cdiv((long long)N * 40, T), T>>>(x);
    k_scatter<128, 160, false><<<cdiv((long long)E * 32, T), T>>>(x, ei);
    k_mma<160, true><<<gemm_grid, 256, GEMM_SMEM>>>(p_agg, w1[0], b1[0], p_h1, N);
    k_mma<256, true><<<gemm_grid, 256, GEMM_SMEM>>>(p_h1, w2[0], b2[0], p_h2, N);
    k_zero<<<2, 256>>>(p_stats, 512);
    k_stats<<<256, 256>>>(p_h2);
    k_bn_finalize<<<1, 256>>>(gg[0], bb[0]);

    // ---- layers 1,2: din=256, fin=288 (BN affine fused into consumers) ----
    for (int l = 1; l < 3; l++) {
        k_init_agg<256, 288, true><<<cdiv((long long)N * 72, T), T>>>(p_h2);
        k_scatter<256, 288, true><<<cdiv((long long)E * 64, T), T>>>(p_h2, ei);
        k_mma<288, true><<<gemm_grid, 256, GEMM_SMEM>>>(p_agg, w1[l], b1[l], p_h1, N);
        k_mma<256, true><<<gemm_grid, 256, GEMM_SMEM>>>(p_h1, w2[l], b2[l], p_h2, N);
        k_zero<<<2, 256>>>(p_stats, 512);
        k_stats<<<256, 256>>>(p_h2);
        k_bn_finalize<<<1, 256>>>(gg[l], bb[l]);
    }

    // ---- pooling (final BN affine fused) ----
    k_zero<<<cdiv(N_FRAG + N_GRAPH, T), T>>>(p_cnt, N_FRAG + N_GRAPH);
    k_zero<<<cdiv(out_size, T), T>>>(out, out_size);
    k_count<<<cdiv(N, T), T>>>(frag, graph);
    k_pool<<<cdiv((long long)N * 64, T), T>>>(frag, graph, p_h2, out);
}

// round 8
// speedup vs baseline: 2.5231x; 1.0110x over previous
#include <cuda_runtime.h>
#include <math.h>

// ---------------- problem constants ----------------
constexpr int N       = 50000;
constexpr int E       = 200000;
constexpr int D_E     = 32;
constexpr int N_FRAG  = 10000;
constexpr int N_GRAPH = 2000;
constexpr float BN_EPS = 1e-5f;

// ---------------- scratch (device globals; no allocation allowed) ----------------
__device__ __align__(16) float g_agg [(size_t)N * 288];   // max fin = 288
__device__ __align__(16) float g_h1  [(size_t)N * 256];
__device__ __align__(16) float g_h2  [(size_t)N * 256];
__device__ __align__(16) float g_agge[(size_t)N * 32];
__device__ float g_stats[512];
__device__ float g_scale[256];
__device__ float g_bias [256];
__device__ float g_cnt  [N_FRAG + N_GRAPH];

// ---------------- small helpers ----------------
__global__ void k_zero(float* p, int n) {
    for (int i = blockIdx.x * blockDim.x + threadIdx.x; i < n; i += gridDim.x * blockDim.x)
        p[i] = 0.f;
}

__device__ __forceinline__ void red_v4(float* p, float a, float b, float c, float d) {
    asm volatile("red.global.add.v4.f32 [%0], {%1,%2,%3,%4};"
                 :: "l"(p), "f"(a), "f"(b), "f"(c), "f"(d) : "memory");
}

__device__ __forceinline__ unsigned f2tf32(float x) {
    unsigned r;
    asm("cvt.rna.tf32.f32 %0, %1;" : "=r"(r) : "f"(x));
    return r;
}
// hi/lo split: hi = tf32(v), lo = tf32(v - hi)
__device__ __forceinline__ void split_tf32(float v, unsigned& hi, unsigned& lo) {
    hi = f2tf32(v);
    lo = f2tf32(v - __uint_as_float(hi));
}

#define MMA_TF32(c, a, b)                                                     \
    asm volatile(                                                             \
        "mma.sync.aligned.m16n8k8.row.col.f32.tf32.tf32.f32 "                 \
        "{%0,%1,%2,%3}, {%4,%5,%6,%7}, {%8,%9}, {%0,%1,%2,%3};"               \
        : "+f"((c)[0]), "+f"((c)[1]), "+f"((c)[2]), "+f"((c)[3])              \
        : "r"((a)[0]), "r"((a)[1]), "r"((a)[2]), "r"((a)[3]),                 \
          "r"((b)[0]), "r"((b)[1]))

// edge-feature aggregate: g_agge[dst] += relu(edge_attr[e])  (layer-invariant)
__global__ void k_edge_agg(const float* __restrict__ ea, const int* __restrict__ ei) {
    int i = blockIdx.x * blockDim.x + threadIdx.x;
    if (i >= E * (D_E / 4)) return;
    int e = i >> 3, c4 = (i & 7) * 4;
    float4 v = *(const float4*)(ea + (size_t)e * D_E + c4);
    int d = ei[E + e];
    red_v4(&g_agge[(size_t)d * D_E + c4],
           fmaxf(v.x, 0.f), fmaxf(v.y, 0.f), fmaxf(v.z, 0.f), fmaxf(v.w, 0.f));
}

// agg[:, :DIN] = affine?(in*scale+bias):in (residual), agg[:, DIN:FIN] = g_agge
template<int DIN, int FIN, bool AFF>
__global__ void k_init_agg(const float* __restrict__ in) {
    int i = blockIdx.x * blockDim.x + threadIdx.x;
    constexpr int CG = FIN / 4;
    if (i >= N * CG) return;
    int n = i / CG, c = (i - n * CG) * 4;
    float4 v;
    if (c < DIN) {
        v = *(const float4*)(in + (size_t)n * DIN + c);
        if (AFF) {
            v.x = fmaf(v.x, g_scale[c],     g_bias[c]);
            v.y = fmaf(v.y, g_scale[c + 1], g_bias[c + 1]);
            v.z = fmaf(v.z, g_scale[c + 2], g_bias[c + 2]);
            v.w = fmaf(v.w, g_scale[c + 3], g_bias[c + 3]);
        }
    } else {
        v = *(const float4*)(&g_agge[(size_t)n * D_E + (c - DIN)]);
    }
    *(float4*)(&g_agg[(size_t)n * FIN + c]) = v;
}

// agg[dst, :DIN] += relu(affine?(in*scale+bias):in [src])
template<int DIN, int FIN, bool AFF>
__global__ void k_scatter(const float* __restrict__ in, const int* __restrict__ ei) {
    int i = blockIdx.x * blockDim.x + threadIdx.x;
    constexpr int CG = DIN / 4;
    if (i >= E * CG) return;
    int e = i / CG, c = (i - e * CG) * 4;
    int s = ei[e], d = ei[E + e];
    float4 v = *(const float4*)(in + (size_t)s * DIN + c);
    if (AFF) {
        v.x = fmaf(v.x, g_scale[c],     g_bias[c]);
        v.y = fmaf(v.y, g_scale[c + 1], g_bias[c + 1]);
        v.z = fmaf(v.z, g_scale[c + 2], g_bias[c + 2]);
        v.w = fmaf(v.w, g_scale[c + 3], g_bias[c + 3]);
    }
    red_v4(&g_agg[(size_t)d * FIN + c],
           fmaxf(v.x, 0.f), fmaxf(v.y, 0.f), fmaxf(v.z, 0.f), fmaxf(v.w, 0.f));
}

// ---------------- 3xTF32 tensor-core GEMM, cp.async double-buffered ----------------
// C[M,256] = relu(A[M,K] @ B[K,256] + bias). Block 128x128x32, 8 warps (2x4),
// warp tile 64x32 via m16n8k8 tf32 mma, hi/lo split in registers:
//   C += Alo*Bhi + Ahi*Blo + Ahi*Bhi
template<int K, bool RELU>
__global__ __launch_bounds__(256, 2) void k_mma(const float* __restrict__ A,
                                                const float* __restrict__ B,
                                                const float* __restrict__ bias,
                                                float* __restrict__ C, int M) {
    constexpr int NC  = 256;
    constexpr int LDA = 36, LDB = 136;
    constexpr int A_T = 128 * LDA;       // 4608 floats
    constexpr int B_T = 32 * LDB;        // 4352 floats
    constexpr int STG = A_T + B_T;       // 8960 floats per stage
    extern __shared__ float dsm[];
    const unsigned sbase = (unsigned)__cvta_generic_to_shared(dsm);

    const int bm = blockIdx.x * 128, bn = blockIdx.y * 128;
    const int tid = threadIdx.x, lane = tid & 31, wid = tid >> 5;
    const int wm = (wid >> 2) * 64, wn = (wid & 3) * 32;
    const int qr = lane >> 2, ql = lane & 3;

    const int a_cg = tid & 7,  a_r0 = tid >> 3;   // A: 8 grp x 32 rows (x4)
    const int b_cg = tid & 31, b_k0 = tid >> 5;   // B: 32 grp x 8 rows (x4)

    auto issue = [&](int k0, int stage) {
        unsigned sb = sbase + stage * (STG * 4);
        #pragma unroll
        for (int q = 0; q < 4; q++) {
            int r = a_r0 + 32 * q;
            int gr = bm + r;
            const float* src = A + (size_t)(gr < M ? gr : M - 1) * K + k0 + a_cg * 4;
            int sz = gr < M ? 16 : 0;
            unsigned dst = sb + (unsigned)(r * LDA + a_cg * 4) * 4;
            asm volatile("cp.async.cg.shared.global [%0], [%1], 16, %2;"
                         :: "r"(dst), "l"(src), "r"(sz));
        }
        #pragma unroll
        for (int q = 0; q < 4; q++) {
            int k = b_k0 + 8 * q;
            const float* src = B + (size_t)(k0 + k) * NC + bn + b_cg * 4;
            unsigned dst = sb + (unsigned)(A_T + k * LDB + b_cg * 4) * 4;
            asm volatile("cp.async.cg.shared.global [%0], [%1], 16, 16;"
                         :: "r"(dst), "l"(src));
        }
        asm volatile("cp.async.commit_group;");
    };

    float acc[4][4][4] = {};
    constexpr int NIT = K / 32;

    issue(0, 0);
    for (int it = 0; it < NIT; ++it) {
        if (it + 1 < NIT) {
            issue((it + 1) * 32, (it + 1) & 1);
            asm volatile("cp.async.wait_group 1;");
        } else {
            asm volatile("cp.async.wait_group 0;");
        }
        __syncthreads();
        const float* As = dsm + (it & 1) * STG;
        const float* Bs = As + A_T;

        #pragma unroll
        for (int kk = 0; kk < 4; kk++) {
            const int kc = kk * 8 + ql;
            unsigned bh[4][2], bl[4][2];
            #pragma unroll
            for (int nf = 0; nf < 4; nf++) {
                int n0 = wn + nf * 8 + qr;
                split_tf32(Bs[kc * LDB + n0],       bh[nf][0], bl[nf][0]);
                split_tf32(Bs[(kc + 4) * LDB + n0], bh[nf][1], bl[nf][1]);
            }
            #pragma unroll
            for (int mf = 0; mf < 4; mf++) {
                int m0 = wm + mf * 16 + qr;
                unsigned ah[4], al[4];
                split_tf32(As[m0 * LDA + kc],           ah[0], al[0]);
                split_tf32(As[(m0 + 8) * LDA + kc],     ah[1], al[1]);
                split_tf32(As[m0 * LDA + kc + 4],       ah[2], al[2]);
                split_tf32(As[(m0 + 8) * LDA + kc + 4], ah[3], al[3]);
                #pragma unroll
                for (int nf = 0; nf < 4; nf++) {
                    float* c = acc[mf][nf];
                    MMA_TF32(c, al, bh[nf]);
                    MMA_TF32(c, ah, bl[nf]);
                    MMA_TF32(c, ah, bh[nf]);
                }
            }
        }
        __syncthreads();
    }

    // epilogue: bias + relu, float2 stores
    #pragma unroll
    for (int mf = 0; mf < 4; mf++) {
        int r0 = bm + wm + mf * 16 + qr;
        #pragma unroll
        for (int nf = 0; nf < 4; nf++) {
            int cc = bn + wn + nf * 8 + ql * 2;
            float b0 = bias[cc], b1 = bias[cc + 1];
            float* c = acc[mf][nf];
            if (r0 < M) {
                float v0 = c[0] + b0, v1 = c[1] + b1;
                if (RELU) { v0 = fmaxf(v0, 0.f); v1 = fmaxf(v1, 0.f); }
                *(float2*)(C + (size_t)r0 * NC + cc) = make_float2(v0, v1);
            }
            if (r0 + 8 < M) {
                float v0 = c[2] + b0, v1 = c[3] + b1;
                if (RELU) { v0 = fmaxf(v0, 0.f); v1 = fmaxf(v1, 0.f); }
                *(float2*)(C + (size_t)(r0 + 8) * NC + cc) = make_float2(v0, v1);
            }
        }
    }
}

// per-column sum / sumsq over h2 (already relu'd)
__global__ void k_stats(const float* __restrict__ h) {
    int c = threadIdx.x;
    int rows = (N + gridDim.x - 1) / gridDim.x;
    int r0 = blockIdx.x * rows;
    int r1 = min(r0 + rows, N);
    float s = 0.f, sq = 0.f;
    for (int r = r0; r < r1; r++) {
        float v = h[(size_t)r * 256 + c];
        s += v; sq += v * v;
    }
    atomicAdd(&g_stats[c], s);
    atomicAdd(&g_stats[256 + c], sq);
}

__global__ void k_bn_finalize(const float* __restrict__ g, const float* __restrict__ beta) {
    int c = threadIdx.x;
    float mu  = g_stats[c] * (1.f / N);
    float var = g_stats[256 + c] * (1.f / N) - mu * mu;
    float sc  = g[c] * rsqrtf(var + BN_EPS);
    g_scale[c] = sc;
    g_bias[c]  = beta[c] - mu * sc;
}

__global__ void k_count(const int* __restrict__ frag, const int* __restrict__ graph) {
    int i = blockIdx.x * blockDim.x + threadIdx.x;
    if (i >= N) return;
    atomicAdd(&g_cnt[frag[i]], 1.f);
    atomicAdd(&g_cnt[N_FRAG + graph[i]], 1.f);
}

// pool reads raw h2 and applies final BN affine inline
__global__ void k_pool(const int* __restrict__ frag, const int* __restrict__ graph,
                       const float* __restrict__ h, float* __restrict__ out) {
    int i = blockIdx.x * blockDim.x + threadIdx.x;
    if (i >= N * 64) return;
    int n = i >> 6, c = (i & 63) * 4;
    float4 v = *(const float4*)(h + (size_t)n * 256 + c);
    v.x = fmaf(v.x, g_scale[c],     g_bias[c]);
    v.y = fmaf(v.y, g_scale[c + 1], g_bias[c + 1]);
    v.z = fmaf(v.z, g_scale[c + 2], g_bias[c + 2]);
    v.w = fmaf(v.w, g_scale[c + 3], g_bias[c + 3]);
    int bf = frag[n];
    int bg = graph[n];
    float wf = rsqrtf(fmaxf(g_cnt[bf], 1.f));
    float wg = rsqrtf(fmaxf(g_cnt[N_FRAG + bg], 1.f));
    red_v4(out + (size_t)bf * 256 + c, v.x * wf, v.y * wf, v.z * wf, v.w * wf);
    red_v4(out + (size_t)(N_FRAG + bg) * 256 + c, v.x * wg, v.y * wg, v.z * wg, v.w * wg);
}

// ---------------- launch ----------------
static inline int cdiv(long long a, int b) { return (int)((a + b - 1) / b); }
constexpr int GEMM_SMEM = 2 * (128 * 36 + 32 * 136) * 4;   // 71680 bytes

extern "C" void kernel_launch(void* const* d_in, const int* in_sizes, int n_in,
                              void* d_out, int out_size) {
    // resolve input ordering by size signature (edge_index is unique 2*E entry)
    int idx_ei = -1;
    for (int i = 0; i < n_in; i++) if (in_sizes[i] == 2 * E) { idx_ei = i; break; }

    int ix, iea, ifr, igr;
    int iw1[3], ib1[3], iw2[3], ib2[3], ig[3], ibeta[3];
    if (idx_ei == 10) {              // alphabetical
        ix = 22; iea = 9; ifr = 11; igr = 15;
        for (int l = 0; l < 3; l++) {
            ib1[l] = 0 + l; ib2[l] = 3 + l; ibeta[l] = 6 + l;
            ig[l] = 12 + l; iw1[l] = 16 + l; iw2[l] = 19 + l;
        }
    } else {                         // dict / reference-signature order
        idx_ei = 2;
        ix = 0; iea = 1; ifr = 3; igr = 4;
        for (int l = 0; l < 3; l++) {
            iw1[l] = 5 + 6 * l + 0; ib1[l] = 5 + 6 * l + 1;
            iw2[l] = 5 + 6 * l + 2; ib2[l] = 5 + 6 * l + 3;
            ig[l]  = 5 + 6 * l + 4; ibeta[l] = 5 + 6 * l + 5;
        }
    }

    const float* x     = (const float*)d_in[ix];
    const float* ea    = (const float*)d_in[iea];
    const int*   ei    = (const int*)d_in[idx_ei];
    const int*   frag  = (const int*)d_in[ifr];
    const int*   graph = (const int*)d_in[igr];
    const float* w1[3]; const float* b1[3]; const float* w2[3];
    const float* b2[3]; const float* gg[3]; const float* bb[3];
    for (int l = 0; l < 3; l++) {
        w1[l] = (const float*)d_in[iw1[l]];
        b1[l] = (const float*)d_in[ib1[l]];
        w2[l] = (const float*)d_in[iw2[l]];
        b2[l] = (const float*)d_in[ib2[l]];
        gg[l] = (const float*)d_in[ig[l]];
        bb[l] = (const float*)d_in[ibeta[l]];
    }
    float* out = (float*)d_out;

    float* p_agge; cudaGetSymbolAddress((void**)&p_agge, g_agge);
    float* p_stats; cudaGetSymbolAddress((void**)&p_stats, g_stats);
    float* p_cnt;  cudaGetSymbolAddress((void**)&p_cnt, g_cnt);
    float* p_agg;  cudaGetSymbolAddress((void**)&p_agg, g_agg);
    float* p_h1;   cudaGetSymbolAddress((void**)&p_h1, g_h1);
    float* p_h2;   cudaGetSymbolAddress((void**)&p_h2, g_h2);

    cudaFuncSetAttribute(k_mma<160, true>, cudaFuncAttributeMaxDynamicSharedMemorySize, GEMM_SMEM);
    cudaFuncSetAttribute(k_mma<256, true>, cudaFuncAttributeMaxDynamicSharedMemorySize, GEMM_SMEM);
    cudaFuncSetAttribute(k_mma<288, true>, cudaFuncAttributeMaxDynamicSharedMemorySize, GEMM_SMEM);

    const int T = 256;
    dim3 gemm_grid(cdiv(N, 128), 2);

    // edge-feature aggregate (layer-invariant)
    k_zero<<<cdiv(N * D_E, T), T>>>(p_agge, N * D_E);
    k_edge_agg<<<cdiv((long long)E * 8, T), T>>>(ea, ei);

    // ---- layer 0: din=128, fin=160 ----
    k_init_agg<128, 160, false><<<cdiv((long long)N * 40, T), T>>>(x);
    k_scatter<128, 160, false><<<cdiv((long long)E * 32, T), T>>>(x, ei);
    k_mma<160, true><<<gemm_grid, 256, GEMM_SMEM>>>(p_agg, w1[0], b1[0], p_h1, N);
    k_mma<256, true><<<gemm_grid, 256, GEMM_SMEM>>>(p_h1, w2[0], b2[0], p_h2, N);
    k_zero<<<2, 256>>>(p_stats, 512);
    k_stats<<<256, 256>>>(p_h2);
    k_bn_finalize<<<1, 256>>>(gg[0], bb[0]);

    // ---- layers 1,2: din=256, fin=288 (BN affine fused into consumers) ----
    for (int l = 1; l < 3; l++) {
        k_init_agg<256, 288, true><<<cdiv((long long)N * 72, T), T>>>(p_h2);
        k_scatter<256, 288, true><<<cdiv((long long)E * 64, T), T>>>(p_h2, ei);
        k_mma<288, true><<<gemm_grid, 256, GEMM_SMEM>>>(p_agg, w1[l], b1[l], p_h1, N);
        k_mma<256, true><<<gemm_grid, 256, GEMM_SMEM>>>(p_h1, w2[l], b2[l], p_h2, N);
        k_zero<<<2, 256>>>(p_stats, 512);
        k_stats<<<256, 256>>>(p_h2);
        k_bn_finalize<<<1, 256>>>(gg[l], bb[l]);
    }

    // ---- pooling (final BN affine fused) ----
    k_zero<<<cdiv(N_FRAG + N_GRAPH, T), T>>>(p_cnt, N_FRAG + N_GRAPH);
    k_zero<<<cdiv(out_size, T), T>>>(out, out_size);
    k_count<<<cdiv(N, T), T>>>(frag, graph);
    k_pool<<<cdiv((long long)N * 64, T), T>>>(frag, graph, p_h2, out);
}

// round 10
// speedup vs baseline: 3.4297x; 1.3593x over previous
#include <cuda_runtime.h>
#include <math.h>
#include <stdint.h>

// ---------------- problem constants ----------------
constexpr int N       = 50000;
constexpr int E       = 200000;
constexpr int D_E     = 32;
constexpr int N_FRAG  = 10000;
constexpr int N_GRAPH = 2000;
constexpr float BN_EPS = 1e-5f;

// ---------------- scratch (device globals; no allocation allowed) ----------------
__device__ __align__(16) float g_agg [(size_t)N * 288];   // max fin = 288
__device__ __align__(16) float g_h1  [(size_t)N * 256];
__device__ __align__(16) float g_h2  [(size_t)N * 256];
__device__ __align__(16) float g_agge[(size_t)N * 32];
__device__ float g_stats[512];
__device__ float g_scale[256];
__device__ float g_bias [256];
__device__ float g_cnt  [N_FRAG + N_GRAPH];

// ---------------- small helpers ----------------
__global__ void k_zero(float* p, int n) {
    for (int i = blockIdx.x * blockDim.x + threadIdx.x; i < n; i += gridDim.x * blockDim.x)
        p[i] = 0.f;
}

__device__ __forceinline__ void red_v4(float* p, float a, float b, float c, float d) {
    asm volatile("red.global.add.v4.f32 [%0], {%1,%2,%3,%4};"
                 :: "l"(p), "f"(a), "f"(b), "f"(c), "f"(d) : "memory");
}

// pack two floats to bf16x2: result.lo = bf16(a), result.hi = bf16(b)
__device__ __forceinline__ uint32_t pk(float a, float b) {
    uint32_t r;
    asm("cvt.rn.bf16x2.f32 %0, %1, %2;" : "=r"(r) : "f"(b), "f"(a));
    return r;
}
__device__ __forceinline__ float lo_f(uint32_t p) { return __uint_as_float(p << 16); }
__device__ __forceinline__ float hi_f(uint32_t p) { return __uint_as_float(p & 0xFFFF0000u); }
// residual (lo) plane for a packed hi pair
__device__ __forceinline__ uint32_t resid(uint32_t h, float a, float b) {
    return pk(a - lo_f(h), b - hi_f(h));
}

#define MMA_BF16(c, a, b)                                                     \
    asm volatile(                                                             \
        "mma.sync.aligned.m16n8k16.row.col.f32.bf16.bf16.f32 "                \
        "{%0,%1,%2,%3}, {%4,%5,%6,%7}, {%8,%9}, {%0,%1,%2,%3};"               \
        : "+f"((c)[0]), "+f"((c)[1]), "+f"((c)[2]), "+f"((c)[3])              \
        : "r"((a)[0]), "r"((a)[1]), "r"((a)[2]), "r"((a)[3]),                 \
          "r"((b)[0]), "r"((b)[1]))

// edge-feature aggregate: g_agge[dst] += relu(edge_attr[e])  (layer-invariant)
__global__ void k_edge_agg(const float* __restrict__ ea, const int* __restrict__ ei) {
    int i = blockIdx.x * blockDim.x + threadIdx.x;
    if (i >= E * (D_E / 4)) return;
    int e = i >> 3, c4 = (i & 7) * 4;
    float4 v = *(const float4*)(ea + (size_t)e * D_E + c4);
    int d = ei[E + e];
    red_v4(&g_agge[(size_t)d * D_E + c4],
           fmaxf(v.x, 0.f), fmaxf(v.y, 0.f), fmaxf(v.z, 0.f), fmaxf(v.w, 0.f));
}

// agg[:, :DIN] = affine?(in*scale+bias):in (residual), agg[:, DIN:FIN] = g_agge
template<int DIN, int FIN, bool AFF>
__global__ void k_init_agg(const float* __restrict__ in) {
    int i = blockIdx.x * blockDim.x + threadIdx.x;
    constexpr int CG = FIN / 4;
    if (i >= N * CG) return;
    int n = i / CG, c = (i - n * CG) * 4;
    float4 v;
    if (c < DIN) {
        v = *(const float4*)(in + (size_t)n * DIN + c);
        if (AFF) {
            v.x = fmaf(v.x, g_scale[c],     g_bias[c]);
            v.y = fmaf(v.y, g_scale[c + 1], g_bias[c + 1]);
            v.z = fmaf(v.z, g_scale[c + 2], g_bias[c + 2]);
            v.w = fmaf(v.w, g_scale[c + 3], g_bias[c + 3]);
        }
    } else {
        v = *(const float4*)(&g_agge[(size_t)n * D_E + (c - DIN)]);
    }
    *(float4*)(&g_agg[(size_t)n * FIN + c]) = v;
}

// agg[dst, :DIN] += relu(affine?(in*scale+bias):in [src])
template<int DIN, int FIN, bool AFF>
__global__ void k_scatter(const float* __restrict__ in, const int* __restrict__ ei) {
    int i = blockIdx.x * blockDim.x + threadIdx.x;
    constexpr int CG = DIN / 4;
    if (i >= E * CG) return;
    int e = i / CG, c = (i - e * CG) * 4;
    int s = ei[e], d = ei[E + e];
    float4 v = *(const float4*)(in + (size_t)s * DIN + c);
    if (AFF) {
        v.x = fmaf(v.x, g_scale[c],     g_bias[c]);
        v.y = fmaf(v.y, g_scale[c + 1], g_bias[c + 1]);
        v.z = fmaf(v.z, g_scale[c + 2], g_bias[c + 2]);
        v.w = fmaf(v.w, g_scale[c + 3], g_bias[c + 3]);
    }
    red_v4(&g_agg[(size_t)d * FIN + c],
           fmaxf(v.x, 0.f), fmaxf(v.y, 0.f), fmaxf(v.z, 0.f), fmaxf(v.w, 0.f));
}

// ---------------- 3xBF16 tensor-core GEMM, cp.async double-buffered ----------------
// C[M,256] = relu(A[M,K] @ B[K,256] + bias). Block 128x128x32, 8 warps (2x4),
// warp tile 64x32 via m16n8k16 bf16 mma, hi/lo split in registers:
//   C += Alo*Bhi + Ahi*Blo + Ahi*Bhi   (~15-bit effective mantissa)
template<int K, bool RELU>
__global__ __launch_bounds__(256, 2) void k_mma(const float* __restrict__ A,
                                                const float* __restrict__ B,
                                                const float* __restrict__ bias,
                                                float* __restrict__ C, int M) {
    constexpr int NC  = 256;
    constexpr int LDA = 40, LDB = 136;   // LDA 40: conflict-free float2 frag loads
    constexpr int A_T = 128 * LDA;       // 5120 floats
    constexpr int B_T = 32 * LDB;        // 4352 floats
    constexpr int STG = A_T + B_T;       // 9472 floats per stage
    extern __shared__ float dsm[];
    const unsigned sbase = (unsigned)__cvta_generic_to_shared(dsm);

    const int bm = blockIdx.x * 128, bn = blockIdx.y * 128;
    const int tid = threadIdx.x, lane = tid & 31, wid = tid >> 5;
    const int wm = (wid >> 2) * 64, wn = (wid & 3) * 32;
    const int qr = lane >> 2, ql = lane & 3;

    const int a_cg = tid & 7,  a_r0 = tid >> 3;   // A: 8 grp x 32 rows (x4)
    const int b_cg = tid & 31, b_k0 = tid >> 5;   // B: 32 grp x 8 rows (x4)

    auto issue = [&](int k0, int stage) {
        unsigned sb = sbase + stage * (STG * 4);
        #pragma unroll
        for (int q = 0; q < 4; q++) {
            int r = a_r0 + 32 * q;
            int gr = bm + r;
            const float* src = A + (size_t)(gr < M ? gr : M - 1) * K + k0 + a_cg * 4;
            int sz = gr < M ? 16 : 0;
            unsigned dst = sb + (unsigned)(r * LDA + a_cg * 4) * 4;
            asm volatile("cp.async.cg.shared.global [%0], [%1], 16, %2;"
                         :: "r"(dst), "l"(src), "r"(sz));
        }
        #pragma unroll
        for (int q = 0; q < 4; q++) {
            int k = b_k0 + 8 * q;
            const float* src = B + (size_t)(k0 + k) * NC + bn + b_cg * 4;
            unsigned dst = sb + (unsigned)(A_T + k * LDB + b_cg * 4) * 4;
            asm volatile("cp.async.cg.shared.global [%0], [%1], 16, 16;"
                         :: "r"(dst), "l"(src));
        }
        asm volatile("cp.async.commit_group;");
    };

    float acc[4][4][4] = {};
    constexpr int NIT = K / 32;

    issue(0, 0);
    for (int it = 0; it < NIT; ++it) {
        if (it + 1 < NIT) {
            issue((it + 1) * 32, (it + 1) & 1);
            asm volatile("cp.async.wait_group 1;");
        } else {
            asm volatile("cp.async.wait_group 0;");
        }
        __syncthreads();
        const float* As = dsm + (it & 1) * STG;
        const float* Bs = As + A_T;

        #pragma unroll
        for (int ks = 0; ks < 2; ks++) {          // two k16 steps per k32 tile
            const int kc = ks * 16 + ql * 2;
            uint32_t bh[4][2], bl[4][2];
            #pragma unroll
            for (int nf = 0; nf < 4; nf++) {
                int n0 = wn + nf * 8 + qr;
                float v0 = Bs[kc * LDB + n0];
                float v1 = Bs[(kc + 1) * LDB + n0];
                float v8 = Bs[(kc + 8) * LDB + n0];
                float v9 = Bs[(kc + 9) * LDB + n0];
                bh[nf][0] = pk(v0, v1);  bl[nf][0] = resid(bh[nf][0], v0, v1);
                bh[nf][1] = pk(v8, v9);  bl[nf][1] = resid(bh[nf][1], v8, v9);
            }
            #pragma unroll
            for (int mf = 0; mf < 4; mf++) {
                int m0 = wm + mf * 16 + qr;
                float2 p0 = *(const float2*)&As[m0 * LDA + kc];
                float2 p1 = *(const float2*)&As[(m0 + 8) * LDA + kc];
                float2 p2 = *(const float2*)&As[m0 * LDA + kc + 8];
                float2 p3 = *(const float2*)&As[(m0 + 8) * LDA + kc + 8];
                uint32_t ah[4], al[4];
                ah[0] = pk(p0.x, p0.y); al[0] = resid(ah[0], p0.x, p0.y);
                ah[1] = pk(p1.x, p1.y); al[1] = resid(ah[1], p1.x, p1.y);
                ah[2] = pk(p2.x, p2.y); al[2] = resid(ah[2], p2.x, p2.y);
                ah[3] = pk(p3.x, p3.y); al[3] = resid(ah[3], p3.x, p3.y);
                #pragma unroll
                for (int nf = 0; nf < 4; nf++) {
                    float* c = acc[mf][nf];
                    MMA_BF16(c, al, bh[nf]);
                    MMA_BF16(c, ah, bl[nf]);
                    MMA_BF16(c, ah, bh[nf]);
                }
            }
        }
        __syncthreads();
    }

    // epilogue: bias + relu, float2 stores (acc layout identical to k8 case)
    #pragma unroll
    for (int mf = 0; mf < 4; mf++) {
        int r0 = bm + wm + mf * 16 + qr;
        #pragma unroll
        for (int nf = 0; nf < 4; nf++) {
            int cc = bn + wn + nf * 8 + ql * 2;
            float b0 = bias[cc], b1 = bias[cc + 1];
            float* c = acc[mf][nf];
            if (r0 < M) {
                float v0 = c[0] + b0, v1 = c[1] + b1;
                if (RELU) { v0 = fmaxf(v0, 0.f); v1 = fmaxf(v1, 0.f); }
                *(float2*)(C + (size_t)r0 * NC + cc) = make_float2(v0, v1);
            }
            if (r0 + 8 < M) {
                float v0 = c[2] + b0, v1 = c[3] + b1;
                if (RELU) { v0 = fmaxf(v0, 0.f); v1 = fmaxf(v1, 0.f); }
                *(float2*)(C + (size_t)(r0 + 8) * NC + cc) = make_float2(v0, v1);
            }
        }
    }
}

// per-column sum / sumsq over h2 (already relu'd)
__global__ void k_stats(const float* __restrict__ h) {
    int c = threadIdx.x;
    int rows = (N + gridDim.x - 1) / gridDim.x;
    int r0 = blockIdx.x * rows;
    int r1 = min(r0 + rows, N);
    float s = 0.f, sq = 0.f;
    for (int r = r0; r < r1; r++) {
        float v = h[(size_t)r * 256 + c];
        s += v; sq += v * v;
    }
    atomicAdd(&g_stats[c], s);
    atomicAdd(&g_stats[256 + c], sq);
}

__global__ void k_bn_finalize(const float* __restrict__ g, const float* __restrict__ beta) {
    int c = threadIdx.x;
    float mu  = g_stats[c] * (1.f / N);
    float var = g_stats[256 + c] * (1.f / N) - mu * mu;
    float sc  = g[c] * rsqrtf(var + BN_EPS);
    g_scale[c] = sc;
    g_bias[c]  = beta[c] - mu * sc;
}

__global__ void k_count(const int* __restrict__ frag, const int* __restrict__ graph) {
    int i = blockIdx.x * blockDim.x + threadIdx.x;
    if (i >= N) return;
    atomicAdd(&g_cnt[frag[i]], 1.f);
    atomicAdd(&g_cnt[N_FRAG + graph[i]], 1.f);
}

// pool reads raw h2 and applies final BN affine inline
__global__ void k_pool(const int* __restrict__ frag, const int* __restrict__ graph,
                       const float* __restrict__ h, float* __restrict__ out) {
    int i = blockIdx.x * blockDim.x + threadIdx.x;
    if (i >= N * 64) return;
    int n = i >> 6, c = (i & 63) * 4;
    float4 v = *(const float4*)(h + (size_t)n * 256 + c);
    v.x = fmaf(v.x, g_scale[c],     g_bias[c]);
    v.y = fmaf(v.y, g_scale[c + 1], g_bias[c + 1]);
    v.z = fmaf(v.z, g_scale[c + 2], g_bias[c + 2]);
    v.w = fmaf(v.w, g_scale[c + 3], g_bias[c + 3]);
    int bf = frag[n];
    int bg = graph[n];
    float wf = rsqrtf(fmaxf(g_cnt[bf], 1.f));
    float wg = rsqrtf(fmaxf(g_cnt[N_FRAG + bg], 1.f));
    red_v4(out + (size_t)bf * 256 + c, v.x * wf, v.y * wf, v.z * wf, v.w * wf);
    red_v4(out + (size_t)(N_FRAG + bg) * 256 + c, v.x * wg, v.y * wg, v.z * wg, v.w * wg);
}

// ---------------- launch ----------------
static inline int cdiv(long long a, int b) { return (int)((a + b - 1) / b); }
constexpr int GEMM_SMEM = 2 * (128 * 40 + 32 * 136) * 4;   // 75776 bytes

extern "C" void kernel_launch(void* const* d_in, const int* in_sizes, int n_in,
                              void* d_out, int out_size) {
    // resolve input ordering by size signature (edge_index is unique 2*E entry)
    int idx_ei = -1;
    for (int i = 0; i < n_in; i++) if (in_sizes[i] == 2 * E) { idx_ei = i; break; }

    int ix, iea, ifr, igr;
    int iw1[3], ib1[3], iw2[3], ib2[3], ig[3], ibeta[3];
    if (idx_ei == 10) {              // alphabetical
        ix = 22; iea = 9; ifr = 11; igr = 15;
        for (int l = 0; l < 3; l++) {
            ib1[l] = 0 + l; ib2[l] = 3 + l; ibeta[l] = 6 + l;
            ig[l] = 12 + l; iw1[l] = 16 + l; iw2[l] = 19 + l;
        }
    } else {                         // dict / reference-signature order
        idx_ei = 2;
        ix = 0; iea = 1; ifr = 3; igr = 4;
        for (int l = 0; l < 3; l++) {
            iw1[l] = 5 + 6 * l + 0; ib1[l] = 5 + 6 * l + 1;
            iw2[l] = 5 + 6 * l + 2; ib2[l] = 5 + 6 * l + 3;
            ig[l]  = 5 + 6 * l + 4; ibeta[l] = 5 + 6 * l + 5;
        }
    }

    const float* x     = (const float*)d_in[ix];
    const float* ea    = (const float*)d_in[iea];
    const int*   ei    = (const int*)d_in[idx_ei];
    const int*   frag  = (const int*)d_in[ifr];
    const int*   graph = (const int*)d_in[igr];
    const float* w1[3]; const float* b1[3]; const float* w2[3];
    const float* b2[3]; const float* gg[3]; const float* bb[3];
    for (int l = 0; l < 3; l++) {
        w1[l] = (const float*)d_in[iw1[l]];
        b1[l] = (const float*)d_in[ib1[l]];
        w2[l] = (const float*)d_in[iw2[l]];
        b2[l] = (const float*)d_in[ib2[l]];
        gg[l] = (const float*)d_in[ig[l]];
        bb[l] = (const float*)d_in[ibeta[l]];
    }
    float* out = (float*)d_out;

    float* p_agge; cudaGetSymbolAddress((void**)&p_agge, g_agge);
    float* p_stats; cudaGetSymbolAddress((void**)&p_stats, g_stats);
    float* p_cnt;  cudaGetSymbolAddress((void**)&p_cnt, g_cnt);
    float* p_agg;  cudaGetSymbolAddress((void**)&p_agg, g_agg);
    float* p_h1;   cudaGetSymbolAddress((void**)&p_h1, g_h1);
    float* p_h2;   cudaGetSymbolAddress((void**)&p_h2, g_h2);

    cudaFuncSetAttribute(k_mma<160, true>, cudaFuncAttributeMaxDynamicSharedMemorySize, GEMM_SMEM);
    cudaFuncSetAttribute(k_mma<256, true>, cudaFuncAttributeMaxDynamicSharedMemorySize, GEMM_SMEM);
    cudaFuncSetAttribute(k_mma<288, true>, cudaFuncAttributeMaxDynamicSharedMemorySize, GEMM_SMEM);

    const int T = 256;
    dim3 gemm_grid(cdiv(N, 128), 2);

    // edge-feature aggregate (layer-invariant)
    k_zero<<<cdiv(N * D_E, T), T>>>(p_agge, N * D_E);
    k_edge_agg<<<cdiv((long long)E * 8, T), T>>>(ea, ei);

    // ---- layer 0: din=128, fin=160 ----
    k_init_agg<128, 160, false><<<cdiv((long long)N * 40, T), T>>>(x);
    k_scatter<128, 160, false><<<cdiv((long long)E * 32, T), T>>>(x, ei);
    k_mma<160, true><<<gemm_grid, 256, GEMM_SMEM>>>(p_agg, w1[0], b1[0], p_h1, N);
    k_mma<256, true><<<gemm_grid, 256, GEMM_SMEM>>>(p_h1, w2[0], b2[0], p_h2, N);
    k_zero<<<2, 256>>>(p_stats, 512);
    k_stats<<<256, 256>>>(p_h2);
    k_bn_finalize<<<1, 256>>>(gg[0], bb[0]);

    // ---- layers 1,2: din=256, fin=288 (BN affine fused into consumers) ----
    for (int l = 1; l < 3; l++) {
        k_init_agg<256, 288, true><<<cdiv((long long)N * 72, T), T>>>(p_h2);
        k_scatter<256, 288, true><<<cdiv((long long)E * 64, T), T>>>(p_h2, ei);
        k_mma<288, true><<<gemm_grid, 256, GEMM_SMEM>>>(p_agg, w1[l], b1[l], p_h1, N);
        k_mma<256, true><<<gemm_grid, 256, GEMM_SMEM>>>(p_h1, w2[l], b2[l], p_h2, N);
        k_zero<<<2, 256>>>(p_stats, 512);
        k_stats<<<256, 256>>>(p_h2);
        k_bn_finalize<<<1, 256>>>(gg[l], bb[l]);
    }

    // ---- pooling (final BN affine fused) ----
    k_zero<<<cdiv(N_FRAG + N_GRAPH, T), T>>>(p_cnt, N_FRAG + N_GRAPH);
    k_zero<<<cdiv(out_size, T), T>>>(out, out_size);
    k_count<<<cdiv(N, T), T>>>(frag, graph);
    k_pool<<<cdiv((long long)N * 64, T), T>>>(frag, graph, p_h2, out);
}

// round 14
// speedup vs baseline: 3.5506x; 1.0353x over previous
#include <cuda_runtime.h>
#include <cuda_bf16.h>
#include <math.h>
#include <stdint.h>

constexpr int N = 50000, E = 200000, D_E = 32, N_FRAG = 10000, N_GRAPH = 2000;
constexpr float BN_EPS = 1e-5f;
constexpr int KPAD = 320;

// ---------------- scratch ----------------
__device__ __align__(16) float g_agg [(size_t)N * 288];
__device__ __align__(16) float g_h1  [(size_t)N * 256];
__device__ __align__(16) float g_h2  [(size_t)N * 256];
__device__ __align__(16) float g_agge[(size_t)N * 32];
__device__ float g_stats[512], g_scale[256], g_bias[256], g_cnt[N_FRAG + N_GRAPH];
__device__ __align__(16) __nv_bfloat16 g_wsp[6][2][256 * KPAD];  // weight hi/lo planes, [n][k]

// ---------------- helpers ----------------
__global__ void k_zero(float* p, int n) {
    for (int i = blockIdx.x * blockDim.x + threadIdx.x; i < n; i += gridDim.x * blockDim.x)
        p[i] = 0.f;
}
__device__ __forceinline__ void red_v4(float* p, float a, float b, float c, float d) {
    asm volatile("red.global.add.v4.f32 [%0], {%1,%2,%3,%4};"
                 :: "l"(p), "f"(a), "f"(b), "f"(c), "f"(d) : "memory");
}
// pack two floats to bf16x2: lo = bf16(a), hi = bf16(b)
__device__ __forceinline__ uint32_t pk(float a, float b) {
    uint32_t r;
    asm("cvt.rn.bf16x2.f32 %0, %1, %2;" : "=r"(r) : "f"(b), "f"(a));
    return r;
}
__device__ __forceinline__ float lo_f(uint32_t p) { return __uint_as_float(p << 16); }
__device__ __forceinline__ float hi_f(uint32_t p) { return __uint_as_float(p & 0xFFFF0000u); }
__device__ __forceinline__ uint32_t resid(uint32_t h, float a, float b) {
    return pk(a - lo_f(h), b - hi_f(h));
}

#define MMA_BF16(c, a, b)                                                     \
    asm volatile(                                                             \
        "mma.sync.aligned.m16n8k16.row.col.f32.bf16.bf16.f32 "                \
        "{%0,%1,%2,%3}, {%4,%5,%6,%7}, {%8,%9}, {%0,%1,%2,%3};"               \
        : "+f"((c)[0]), "+f"((c)[1]), "+f"((c)[2]), "+f"((c)[3])              \
        : "r"((a)[0]), "r"((a)[1]), "r"((a)[2]), "r"((a)[3]),                 \
          "r"((b)[0]), "r"((b)[1]))

// ---------------- graph kernels ----------------
__global__ void k_edge_agg(const float* __restrict__ ea, const int* __restrict__ ei) {
    int i = blockIdx.x * blockDim.x + threadIdx.x;
    if (i >= E * (D_E / 4)) return;
    int e = i >> 3, c4 = (i & 7) * 4;
    float4 v = *(const float4*)(ea + (size_t)e * D_E + c4);
    int d = ei[E + e];
    red_v4(&g_agge[(size_t)d * D_E + c4],
           fmaxf(v.x, 0.f), fmaxf(v.y, 0.f), fmaxf(v.z, 0.f), fmaxf(v.w, 0.f));
}
template<int DIN, int FIN, bool AFF>
__global__ void k_init_agg(const float* __restrict__ in) {
    int i = blockIdx.x * blockDim.x + threadIdx.x;
    constexpr int CG = FIN / 4;
    if (i >= N * CG) return;
    int n = i / CG, c = (i - n * CG) * 4;
    float4 v;
    if (c < DIN) {
        v = *(const float4*)(in + (size_t)n * DIN + c);
        if (AFF) {
            v.x = fmaf(v.x, g_scale[c],     g_bias[c]);
            v.y = fmaf(v.y, g_scale[c + 1], g_bias[c + 1]);
            v.z = fmaf(v.z, g_scale[c + 2], g_bias[c + 2]);
            v.w = fmaf(v.w, g_scale[c + 3], g_bias[c + 3]);
        }
    } else {
        v = *(const float4*)(&g_agge[(size_t)n * D_E + (c - DIN)]);
    }
    *(float4*)(&g_agg[(size_t)n * FIN + c]) = v;
}
template<int DIN, int FIN, bool AFF>
__global__ void k_scatter(const float* __restrict__ in, const int* __restrict__ ei) {
    int i = blockIdx.x * blockDim.x + threadIdx.x;
    constexpr int CG = DIN / 4;
    if (i >= E * CG) return;
    int e = i / CG, c = (i - e * CG) * 4;
    int s = ei[e], d = ei[E + e];
    float4 v = *(const float4*)(in + (size_t)s * DIN + c);
    if (AFF) {
        v.x = fmaf(v.x, g_scale[c],     g_bias[c]);
        v.y = fmaf(v.y, g_scale[c + 1], g_bias[c + 1]);
        v.z = fmaf(v.z, g_scale[c + 2], g_bias[c + 2]);
        v.w = fmaf(v.w, g_scale[c + 3], g_bias[c + 3]);
    }
    red_v4(&g_agg[(size_t)d * FIN + c],
           fmaxf(v.x, 0.f), fmaxf(v.y, 0.f), fmaxf(v.z, 0.f), fmaxf(v.w, 0.f));
}

// split all 6 weight matrices w[k][n] fp32 -> g_wsp[slot][{hi,lo}][n][KPAD] bf16
struct SplitArgs { const float* w[6]; int k[6]; };
__global__ void k_split_all(SplitArgs a) {
    int z = blockIdx.z;
    const float* w = a.w[z];
    int K = a.k[z];
    __nv_bfloat16* bh = g_wsp[z][0];
    __nv_bfloat16* bl = g_wsp[z][1];
    int i = blockIdx.x * blockDim.x + threadIdx.x;
    if (i >= 64 * K) return;
    int k = i >> 6, n4 = (i & 63) * 4;
    float4 v = *(const float4*)(w + (size_t)k * 256 + n4);
    float vv[4] = {v.x, v.y, v.z, v.w};
    #pragma unroll
    for (int j = 0; j < 4; j++) {
        __nv_bfloat16 h = __float2bfloat16(vv[j]);
        bh[(size_t)(n4 + j) * KPAD + k] = h;
        bl[(size_t)(n4 + j) * KPAD + k] = __float2bfloat16(vv[j] - __bfloat162float(h));
    }
}

// ---------------- 3xBF16 GEMM: A fp32 smem (frag-time split), B pre-split planes ----------------
// C[M,256] = relu(A[M,K] @ W + bias). Block 128x128, k-chunk 32, 8 warps (2x4),
// warp tile 64x32, m16n8k16: C += Al*Bh + Ah*Bl + Ah*Bh.
// smem: A fp32 2 x 128x40 floats (40960 B); B bf16 planes 2 stages x 2 x 128x80B (40960 B).
constexpr int LDA   = 40;                 // floats
constexpr int A_STG = 128 * LDA;          // 5120 floats / stage
constexpr int OFF_B = 40960;              // B planes base (bytes)
constexpr int GEMM_SMEM = 81920;

template<int K, bool RELU, bool ZSTATS, bool STATS>
__global__ __launch_bounds__(256, 2) void k_mma(const float* __restrict__ A,
                                                const __nv_bfloat16* __restrict__ BHg,
                                                const __nv_bfloat16* __restrict__ BLg,
                                                const float* __restrict__ bias,
                                                float* __restrict__ C, int M) {
    extern __shared__ float dsm[];
    char* dsb = (char*)dsm;
    const unsigned sb = (unsigned)__cvta_generic_to_shared(dsm);

    const int bm = blockIdx.x * 128, bn = blockIdx.y * 128;
    const int tid = threadIdx.x, lane = tid & 31, wid = tid >> 5;
    const int wm = (wid >> 2) * 64, wn = (wid & 3) * 32;
    const int qr = lane >> 2, ql = lane & 3;

    if (ZSTATS && blockIdx.x == 0 && blockIdx.y == 0) {
        g_stats[tid] = 0.f; g_stats[256 + tid] = 0.f;
    }

    const int a_cg = tid & 7,  a_r0 = tid >> 3;   // A: 8 grp x 32 rows (x4)

    auto issue = [&](int k0, int s) {
        // A fp32 tile 128x32, stride 40 floats
        #pragma unroll
        for (int q = 0; q < 4; q++) {
            int r = a_r0 + 32 * q;
            int gr = bm + r;
            const float* src = A + (size_t)(gr < M ? gr : M - 1) * K + k0 + a_cg * 4;
            int sz = gr < M ? 16 : 0;
            unsigned dst = sb + s * (A_STG * 4) + (unsigned)(r * LDA + a_cg * 4) * 4;
            asm volatile("cp.async.cg.shared.global [%0], [%1], 16, %2;"
                         :: "r"(dst), "l"(src), "r"(sz));
        }
        // B bf16 planes: 128 n x 32 k x 2B = 8192 B per plane, 16B units, row stride 80B
        #pragma unroll
        for (int j = 0; j < 4; j++) {
            int gidx = j * 256 + tid;            // 0..1023 : 2 planes x 512 units
            int plane = gidx >> 9, rem = gidx & 511;
            int n = rem >> 2, c = rem & 3;
            const __nv_bfloat16* src = (plane ? BLg : BHg) + (size_t)(bn + n) * KPAD + k0 + c * 8;
            unsigned dst = sb + OFF_B + plane * 20480 + s * 10240 + (unsigned)(n * 80 + c * 16);
            asm volatile("cp.async.cg.shared.global [%0], [%1], 16;" :: "r"(dst), "l"(src));
        }
        asm volatile("cp.async.commit_group;");
    };

    float acc[4][4][4] = {};
    constexpr int NIT = K / 32;

    issue(0, 0);
    for (int it = 0; it < NIT; ++it) {
        const int s = it & 1;
        if (it + 1 < NIT) {
            issue((it + 1) * 32, (it + 1) & 1);
            asm volatile("cp.async.wait_group 1;");
        } else {
            asm volatile("cp.async.wait_group 0;");
        }
        __syncthreads();
        const float* As = dsm + s * A_STG;
        const char* BHp = dsb + OFF_B + s * 10240;
        const char* BLp = dsb + OFF_B + 20480 + s * 10240;

        #pragma unroll
        for (int ks = 0; ks < 2; ks++) {
            const int kc  = ks * 16 + ql * 2;   // A float index within 32-k chunk
            const int kwb = ks * 32 + ql * 4;   // B byte offset within 80B row
            uint32_t bh[4][2], bl[4][2];
            #pragma unroll
            for (int nf = 0; nf < 4; nf++) {
                int nb = (wn + nf * 8 + qr) * 80 + kwb;
                bh[nf][0] = *(const uint32_t*)(BHp + nb);
                bh[nf][1] = *(const uint32_t*)(BHp + nb + 16);
                bl[nf][0] = *(const uint32_t*)(BLp + nb);
                bl[nf][1] = *(const uint32_t*)(BLp + nb + 16);
            }
            #pragma unroll
            for (int mf = 0; mf < 4; mf++) {
                int m0 = wm + mf * 16 + qr;
                float2 p0 = *(const float2*)&As[m0 * LDA + kc];
                float2 p1 = *(const float2*)&As[(m0 + 8) * LDA + kc];
                float2 p2 = *(const float2*)&As[m0 * LDA + kc + 8];
                float2 p3 = *(const float2*)&As[(m0 + 8) * LDA + kc + 8];
                uint32_t ah[4], al[4];
                ah[0] = pk(p0.x, p0.y); al[0] = resid(ah[0], p0.x, p0.y);
                ah[1] = pk(p1.x, p1.y); al[1] = resid(ah[1], p1.x, p1.y);
                ah[2] = pk(p2.x, p2.y); al[2] = resid(ah[2], p2.x, p2.y);
                ah[3] = pk(p3.x, p3.y); al[3] = resid(ah[3], p3.x, p3.y);
                #pragma unroll
                for (int nf = 0; nf < 4; nf++) {
                    float* c = acc[mf][nf];
                    MMA_BF16(c, al, bh[nf]);
                    MMA_BF16(c, ah, bl[nf]);
                    MMA_BF16(c, ah, bh[nf]);
                }
            }
        }
        __syncthreads();
    }

    // ---- epilogue: bias + relu (+ optional fused BN column stats) ----
    float cs[4][2] = {}, cq[4][2] = {};
    #pragma unroll
    for (int mf = 0; mf < 4; mf++) {
        int r0 = bm + wm + mf * 16 + qr;
        #pragma unroll
        for (int nf = 0; nf < 4; nf++) {
            int cc = bn + wn + nf * 8 + ql * 2;
            float b0 = bias[cc], b1 = bias[cc + 1];
            float* c = acc[mf][nf];
            float v0 = c[0] + b0, v1 = c[1] + b1, v2 = c[2] + b0, v3 = c[3] + b1;
            if (RELU) {
                v0 = fmaxf(v0, 0.f); v1 = fmaxf(v1, 0.f);
                v2 = fmaxf(v2, 0.f); v3 = fmaxf(v3, 0.f);
            }
            if (r0 < M) {
                *(float2*)(C + (size_t)r0 * 256 + cc) = make_float2(v0, v1);
                if (STATS) { cs[nf][0] += v0; cs[nf][1] += v1; cq[nf][0] += v0 * v0; cq[nf][1] += v1 * v1; }
            }
            if (r0 + 8 < M) {
                *(float2*)(C + (size_t)(r0 + 8) * 256 + cc) = make_float2(v2, v3);
                if (STATS) { cs[nf][0] += v2; cs[nf][1] += v3; cq[nf][0] += v2 * v2; cq[nf][1] += v3 * v3; }
            }
        }
    }
    if (STATS) {
        #pragma unroll
        for (int nf = 0; nf < 4; nf++)
            #pragma unroll
            for (int h = 0; h < 2; h++) {
                #pragma unroll
                for (int off = 4; off < 32; off <<= 1) {   // reduce across qr lanes
                    cs[nf][h] += __shfl_xor_sync(0xffffffffu, cs[nf][h], off);
                    cq[nf][h] += __shfl_xor_sync(0xffffffffu, cq[nf][h], off);
                }
            }
        if (lane < 4) {
            #pragma unroll
            for (int nf = 0; nf < 4; nf++) {
                int cc = bn + wn + nf * 8 + lane * 2;
                asm volatile("red.global.add.v2.f32 [%0], {%1,%2};"
                             :: "l"(&g_stats[cc]), "f"(cs[nf][0]), "f"(cs[nf][1]) : "memory");
                asm volatile("red.global.add.v2.f32 [%0], {%1,%2};"
                             :: "l"(&g_stats[256 + cc]), "f"(cq[nf][0]), "f"(cq[nf][1]) : "memory");
            }
        }
    }
}

// ---------------- bn / pool ----------------
__global__ void k_bn_finalize(const float* __restrict__ g, const float* __restrict__ beta) {
    int c = threadIdx.x;
    float mu  = g_stats[c] * (1.f / N);
    float var = g_stats[256 + c] * (1.f / N) - mu * mu;
    float sc  = g[c] * rsqrtf(var + BN_EPS);
    g_scale[c] = sc;
    g_bias[c]  = beta[c] - mu * sc;
}
__global__ void k_count(const int* __restrict__ frag, const int* __restrict__ graph) {
    int i = blockIdx.x * blockDim.x + threadIdx.x;
    if (i >= N) return;
    atomicAdd(&g_cnt[frag[i]], 1.f);
    atomicAdd(&g_cnt[N_FRAG + graph[i]], 1.f);
}
__global__ void k_pool(const int* __restrict__ frag, const int* __restrict__ graph,
                       const float* __restrict__ h, float* __restrict__ out) {
    int i = blockIdx.x * blockDim.x + threadIdx.x;
    if (i >= N * 64) return;
    int n = i >> 6, c = (i & 63) * 4;
    float4 v = *(const float4*)(h + (size_t)n * 256 + c);
    v.x = fmaf(v.x, g_scale[c],     g_bias[c]);
    v.y = fmaf(v.y, g_scale[c + 1], g_bias[c + 1]);
    v.z = fmaf(v.z, g_scale[c + 2], g_bias[c + 2]);
    v.w = fmaf(v.w, g_scale[c + 3], g_bias[c + 3]);
    int bf = frag[n], bg = graph[n];
    float wf = rsqrtf(fmaxf(g_cnt[bf], 1.f));
    float wg = rsqrtf(fmaxf(g_cnt[N_FRAG + bg], 1.f));
    red_v4(out + (size_t)bf * 256 + c, v.x * wf, v.y * wf, v.z * wf, v.w * wf);
    red_v4(out + (size_t)(N_FRAG + bg) * 256 + c, v.x * wg, v.y * wg, v.z * wg, v.w * wg);
}

// ---------------- launch ----------------
static inline int cdiv(long long a, int b) { return (int)((a + b - 1) / b); }

extern "C" void kernel_launch(void* const* d_in, const int* in_sizes, int n_in,
                              void* d_out, int out_size) {
    int idx_ei = -1;
    for (int i = 0; i < n_in; i++) if (in_sizes[i] == 2 * E) { idx_ei = i; break; }

    int ix, iea, ifr, igr;
    int iw1[3], ib1[3], iw2[3], ib2[3], ig[3], ibeta[3];
    if (idx_ei == 10) {              // alphabetical
        ix = 22; iea = 9; ifr = 11; igr = 15;
        for (int l = 0; l < 3; l++) {
            ib1[l] = 0 + l; ib2[l] = 3 + l; ibeta[l] = 6 + l;
            ig[l] = 12 + l; iw1[l] = 16 + l; iw2[l] = 19 + l;
        }
    } else {                         // dict / reference-signature order
        idx_ei = 2;
        ix = 0; iea = 1; ifr = 3; igr = 4;
        for (int l = 0; l < 3; l++) {
            iw1[l] = 5 + 6 * l + 0; ib1[l] = 5 + 6 * l + 1;
            iw2[l] = 5 + 6 * l + 2; ib2[l] = 5 + 6 * l + 3;
            ig[l]  = 5 + 6 * l + 4; ibeta[l] = 5 + 6 * l + 5;
        }
    }

    const float* x     = (const float*)d_in[ix];
    const float* ea    = (const float*)d_in[iea];
    const int*   ei    = (const int*)d_in[idx_ei];
    const int*   frag  = (const int*)d_in[ifr];
    const int*   graph = (const int*)d_in[igr];
    const float* w1[3]; const float* b1[3]; const float* w2[3];
    const float* b2[3]; const float* gg[3]; const float* bb[3];
    for (int l = 0; l < 3; l++) {
        w1[l] = (const float*)d_in[iw1[l]];
        b1[l] = (const float*)d_in[ib1[l]];
        w2[l] = (const float*)d_in[iw2[l]];
        b2[l] = (const float*)d_in[ib2[l]];
        gg[l] = (const float*)d_in[ig[l]];
        bb[l] = (const float*)d_in[ibeta[l]];
    }
    float* out = (float*)d_out;

    float* p_agge; cudaGetSymbolAddress((void**)&p_agge, g_agge);
    float* p_cnt;  cudaGetSymbolAddress((void**)&p_cnt, g_cnt);
    float* p_agg;  cudaGetSymbolAddress((void**)&p_agg, g_agg);
    float* p_h1;   cudaGetSymbolAddress((void**)&p_h1, g_h1);
    float* p_h2;   cudaGetSymbolAddress((void**)&p_h2, g_h2);
    __nv_bfloat16* p_w; cudaGetSymbolAddress((void**)&p_w, g_wsp);
    auto slot = [&](int s, int plane) -> const __nv_bfloat16* {
        return p_w + ((size_t)s * 2 + plane) * (256 * KPAD);
    };

    cudaFuncSetAttribute(k_mma<160, true, true,  false>, cudaFuncAttributeMaxDynamicSharedMemorySize, GEMM_SMEM);
    cudaFuncSetAttribute(k_mma<288, true, true,  false>, cudaFuncAttributeMaxDynamicSharedMemorySize, GEMM_SMEM);
    cudaFuncSetAttribute(k_mma<256, true, false, true >, cudaFuncAttributeMaxDynamicSharedMemorySize, GEMM_SMEM);

    const int T = 256;
    dim3 gemm_grid(cdiv(N, 128), 2);

    // split all weights once
    SplitArgs sa;
    sa.w[0] = w1[0]; sa.k[0] = 160;
    sa.w[1] = w2[0]; sa.k[1] = 256;
    sa.w[2] = w1[1]; sa.k[2] = 288;
    sa.w[3] = w2[1]; sa.k[3] = 256;
    sa.w[4] = w1[2]; sa.k[4] = 288;
    sa.w[5] = w2[2]; sa.k[5] = 256;
    dim3 split_grid(cdiv(64 * 288, T), 1, 6);
    k_split_all<<<split_grid, T>>>(sa);

    // edge-feature aggregate (layer-invariant)
    k_zero<<<cdiv(N * D_E, T), T>>>(p_agge, N * D_E);
    k_edge_agg<<<cdiv((long long)E * 8, T), T>>>(ea, ei);

    // ---- layer 0: din=128, fin=160 ----
    k_init_agg<128, 160, false><<<cdiv((long long)N * 40, T), T>>>(x);
    k_scatter<128, 160, false><<<cdiv((long long)E * 32, T), T>>>(x, ei);
    k_mma<160, true, true,  false><<<gemm_grid, 256, GEMM_SMEM>>>(p_agg, slot(0,0), slot(0,1), b1[0], p_h1, N);
    k_mma<256, true, false, true ><<<gemm_grid, 256, GEMM_SMEM>>>(p_h1,  slot(1,0), slot(1,1), b2[0], p_h2, N);
    k_bn_finalize<<<1, 256>>>(gg[0], bb[0]);

    // ---- layers 1,2: din=256, fin=288 (BN affine fused into consumers) ----
    for (int l = 1; l < 3; l++) {
        int s1 = 2 * l, s2 = 2 * l + 1;
        k_init_agg<256, 288, true><<<cdiv((long long)N * 72, T), T>>>(p_h2);
        k_scatter<256, 288, true><<<cdiv((long long)E * 64, T), T>>>(p_h2, ei);
        k_mma<288, true, true,  false><<<gemm_grid, 256, GEMM_SMEM>>>(p_agg, slot(s1,0), slot(s1,1), b1[l], p_h1, N);
        k_mma<256, true, false, true ><<<gemm_grid, 256, GEMM_SMEM>>>(p_h1,  slot(s2,0), slot(s2,1), b2[l], p_h2, N);
        k_bn_finalize<<<1, 256>>>(gg[l], bb[l]);
    }

    // ---- pooling (final BN affine fused) ----
    k_zero<<<cdiv(N_FRAG + N_GRAPH, T), T>>>(p_cnt, N_FRAG + N_GRAPH);
    k_zero<<<cdiv(out_size, T), T>>>(out, out_size);
    k_count<<<cdiv(N, T), T>>>(frag, graph);
    k_pool<<<cdiv((long long)N * 64, T), T>>>(frag, graph, p_h2, out);
}